// round 2
// baseline (speedup 1.0000x reference)
#include <cuda_runtime.h>
#include <cstdint>
#include <cstddef>

#define NB 256
#define FIN 784
#define FH 500
#define NT 100
#define NELEM (NB*FH*NT)      /* 12,800,000 */

// Filter / neuron constants (python doubles rounded to nearest f32, matching
// jnp f32 arithmetic on weak-typed python-float constants)
#define EMC 0.7788007830714049f
#define A1C 1.1466802242428472f
#define A2C (-0.2865047968601901f)

// ---------------- scratch (device globals: no allocations allowed) ----------
__device__ float g_eps[NELEM];
__device__ float g_psp2[NELEM];   // coding, then IIR'd in place -> psp2
__device__ float g_cur2[NELEM];
__device__ float g_psp3[NELEM];

// ---------------- JAX threefry-2x32, key = (0, 42) ---------------------------
__device__ __forceinline__ uint32_t rotl32(uint32_t v, int d) {
  return (v << d) | (v >> (32 - d));
}

__device__ __forceinline__ void threefry_0_42(uint32_t x0, uint32_t x1,
                                              uint32_t& o0, uint32_t& o1) {
  const uint32_t ks0 = 0u;
  const uint32_t ks1 = 42u;
  const uint32_t ks2 = 0x1BD11BDAu ^ 0u ^ 42u;
  x0 += ks0; x1 += ks1;
#define TF_R(d) { x0 += x1; x1 = rotl32(x1, d); x1 ^= x0; }
  TF_R(13) TF_R(15) TF_R(26) TF_R(6)
  x0 += ks1; x1 += ks2 + 1u;
  TF_R(17) TF_R(29) TF_R(16) TF_R(24)
  x0 += ks2; x1 += ks0 + 2u;
  TF_R(13) TF_R(15) TF_R(26) TF_R(6)
  x0 += ks0; x1 += ks1 + 3u;
  TF_R(17) TF_R(29) TF_R(16) TF_R(24)
  x0 += ks1; x1 += ks2 + 4u;
  TF_R(13) TF_R(15) TF_R(26) TF_R(6)
  x0 += ks2; x1 += ks0 + 5u;
#undef TF_R
  o0 = x0; o1 = x1;
}

// XLA ErfInv32 polynomial; mul/add kept separate (XLA's chlo.erf_inv expansion
// emits distinct mul/add HLO ops, no fma contraction).
__device__ __forceinline__ float erfinv_xla(float x) {
  float nx2 = __fmul_rn(x, x);
  float w = -log1pf(-nx2);
  float p;
  if (w < 5.0f) {
    w = __fadd_rn(w, -2.5f);
    p = 2.81022636e-08f;
    p = __fadd_rn(3.43273939e-07f, __fmul_rn(p, w));
    p = __fadd_rn(-3.5233877e-06f, __fmul_rn(p, w));
    p = __fadd_rn(-4.39150654e-06f, __fmul_rn(p, w));
    p = __fadd_rn(0.00021858087f, __fmul_rn(p, w));
    p = __fadd_rn(-0.00125372503f, __fmul_rn(p, w));
    p = __fadd_rn(-0.00417768164f, __fmul_rn(p, w));
    p = __fadd_rn(0.246640727f, __fmul_rn(p, w));
    p = __fadd_rn(1.50140941f, __fmul_rn(p, w));
  } else {
    w = __fadd_rn(sqrtf(w), -3.0f);
    p = -0.000200214257f;
    p = __fadd_rn(0.000100950558f, __fmul_rn(p, w));
    p = __fadd_rn(0.00134934322f, __fmul_rn(p, w));
    p = __fadd_rn(-0.00367342844f, __fmul_rn(p, w));
    p = __fadd_rn(0.00573950773f, __fmul_rn(p, w));
    p = __fadd_rn(-0.0076224613f, __fmul_rn(p, w));
    p = __fadd_rn(0.00943887047f, __fmul_rn(p, w));
    p = __fadd_rn(1.00167406f, __fmul_rn(p, w));
    p = __fadd_rn(2.83297682f, __fmul_rn(p, w));
  }
  return __fmul_rn(p, x);
}

__device__ __forceinline__ float bits_to_normal(uint32_t bits) {
  // JAX uniform: f in [0,1) from top 23 bits; u = f*(hi-lo)+lo with
  // lo = nextafter(-1,0); (hi-lo) rounds (ties-to-even) to exactly 2.0f.
  const float lo = -0.99999994039535522461f;
  float f = __fadd_rn(__uint_as_float((bits >> 9) | 0x3f800000u), -1.0f);
  float u = __fadd_rn(__fmul_rn(f, 2.0f), lo);
  u = fmaxf(u, lo);
  return __fmul_rn(1.4142135623730951f, erfinv_xla(u));  // f32(sqrt(2))
}

// ---------------- kernel 1: eps stream (partitionable threefry) --------------
// Modern JAX default (threefry_partitionable=True): per element index i,
// counter = (i>>32, i&0xffffffff); 32-bit output = out0 ^ out1.
__global__ __launch_bounds__(256) void eps_kernel() {
  uint32_t i = blockIdx.x * 256u + threadIdx.x;
  if (i < NELEM) {
    uint32_t r0, r1;
    threefry_0_42(0u, i, r0, r1);   // hi bits of counter are 0 for n < 2^32
    g_eps[i] = bits_to_normal(r0 ^ r1);
  }
}

// ---------------- kernel 2: GEMM1 + relu + coding ----------------------------
// C[f,t] (mu rows) and C[f+500,t] (ln_var rows), one b per blockIdx.y.
// Block tile: 32 mu-rows (+ paired 32 lnvar-rows) x 100 t. Thread: 4f x 4t x 2.
__global__ __launch_bounds__(256) void gemm1_coding_kernel(
    const float* __restrict__ X, const float* __restrict__ W1,
    const float* __restrict__ b1) {
  __shared__ float Xs[32][128];
  __shared__ float Wm[32][33];
  __shared__ float Wl[32][33];
  int b  = blockIdx.y;
  int f0 = blockIdx.x * 32;
  int tx = threadIdx.x, ty = threadIdx.y;
  int tid = ty * 32 + tx;
  float accm[4][4] = {{0.f}}, accl[4][4] = {{0.f}};

  for (int k0 = 0; k0 < FIN; k0 += 32) {
    for (int i = tid; i < 32 * 128; i += 256) {
      int kk = i >> 7, t = i & 127;
      int k = k0 + kk;
      Xs[kk][t] = (t < NT && k < FIN) ? X[((size_t)b * FIN + k) * NT + t] : 0.f;
    }
    for (int i = tid; i < 32 * 32; i += 256) {
      int fi = i >> 5, kk = i & 31;
      int f = f0 + fi, k = k0 + kk;
      bool ok = (f < FH) && (k < FIN);
      Wm[fi][kk] = ok ? W1[(size_t)f * FIN + k] : 0.f;
      Wl[fi][kk] = ok ? W1[(size_t)(f + FH) * FIN + k] : 0.f;
    }
    __syncthreads();
#pragma unroll
    for (int kk = 0; kk < 32; kk++) {
      float4 xv = reinterpret_cast<const float4*>(&Xs[kk][0])[tx];
      float xa[4] = {xv.x, xv.y, xv.z, xv.w};
#pragma unroll
      for (int j = 0; j < 4; j++) {
        float wm = Wm[ty * 4 + j][kk];
        float wl = Wl[ty * 4 + j][kk];
#pragma unroll
        for (int r = 0; r < 4; r++) {
          accm[j][r] = fmaf(wm, xa[r], accm[j][r]);
          accl[j][r] = fmaf(wl, xa[r], accl[j][r]);
        }
      }
    }
    __syncthreads();
  }

#pragma unroll
  for (int j = 0; j < 4; j++) {
    int f = f0 + ty * 4 + j;
    if (f >= FH) continue;
    float bm = b1[f], bl = b1[f + FH];
#pragma unroll
    for (int r = 0; r < 4; r++) {
      int t = tx * 4 + r;
      if (t < NT) {
        float mu = fmaxf(__fadd_rn(accm[j][r], bm), 0.f);
        float lv = fmaxf(__fadd_rn(accl[j][r], bl), 0.f);
        size_t idx = ((size_t)b * FH + f) * NT + t;
        float sg = expf(__fmul_rn(0.5f, lv));
        g_psp2[idx] = __fadd_rn(mu, __fmul_rn(g_eps[idx], sg));
      }
    }
  }
}

// ---------------- kernel 3: dual-exp IIR in place on g_psp2 ------------------
__global__ __launch_bounds__(256) void iir_kernel() {
  __shared__ float s[64 * 101];
  size_t row0 = (size_t)blockIdx.x * 64;
  int tid = threadIdx.x;
  for (int i = tid; i < 6400; i += 256) {
    int r = i / 100, t = i - r * 100;
    s[r * 101 + t] = g_psp2[row0 * 100 + i];
  }
  __syncthreads();
  if (tid < 64) {
    float y1 = 0.f, y2 = 0.f;
    float* row = &s[tid * 101];
#pragma unroll
    for (int t = 0; t < NT; t++) {
      // y = (A1*y1 + A2*y2) + x  — separate mul/add, XLA association
      float y = __fadd_rn(__fadd_rn(__fmul_rn(A1C, y1), __fmul_rn(A2C, y2)), row[t]);
      row[t] = y;
      y2 = y1; y1 = y;
    }
  }
  __syncthreads();
  for (int i = tid; i < 6400; i += 256) {
    int r = i / 100, t = i - r * 100;
    g_psp2[row0 * 100 + i] = s[r * 101 + t];
  }
}

// ---------------- kernel 4: GEMM2 (cur2 = W2 @ psp2 + b2) --------------------
// Block tile: 64 rows x 100 t; thread: 8f x 4t.
__global__ __launch_bounds__(256) void gemm2_kernel(
    const float* __restrict__ W2, const float* __restrict__ b2) {
  __shared__ float Xs[32][128];
  __shared__ float Ws[64][33];
  int b  = blockIdx.y;
  int f0 = blockIdx.x * 64;
  int tx = threadIdx.x, ty = threadIdx.y;
  int tid = ty * 32 + tx;
  float acc[8][4] = {{0.f}};

  for (int k0 = 0; k0 < FH; k0 += 32) {
    for (int i = tid; i < 32 * 128; i += 256) {
      int kk = i >> 7, t = i & 127;
      int k = k0 + kk;
      Xs[kk][t] = (t < NT && k < FH) ? g_psp2[((size_t)b * FH + k) * NT + t] : 0.f;
    }
    for (int i = tid; i < 64 * 32; i += 256) {
      int fi = i >> 5, kk = i & 31;
      int f = f0 + fi, k = k0 + kk;
      Ws[fi][kk] = (f < FH && k < FH) ? W2[(size_t)f * FH + k] : 0.f;
    }
    __syncthreads();
#pragma unroll
    for (int kk = 0; kk < 32; kk++) {
      float4 xv = reinterpret_cast<const float4*>(&Xs[kk][0])[tx];
      float xa[4] = {xv.x, xv.y, xv.z, xv.w};
#pragma unroll
      for (int j = 0; j < 8; j++) {
        float w = Ws[ty * 8 + j][kk];
#pragma unroll
        for (int r = 0; r < 4; r++) acc[j][r] = fmaf(w, xa[r], acc[j][r]);
      }
    }
    __syncthreads();
  }

#pragma unroll
  for (int j = 0; j < 8; j++) {
    int f = f0 + ty * 8 + j;
    if (f >= FH) continue;
    float bb = b2[f];
#pragma unroll
    for (int r = 0; r < 4; r++) {
      int t = tx * 4 + r;
      if (t < NT)
        g_cur2[((size_t)b * FH + f) * NT + t] = __fadd_rn(acc[j][r], bb);
    }
  }
}

// ---------------- kernel 5: LIF layer 2 fused with second IIR -> psp3 --------
__global__ __launch_bounds__(256) void lif2_psp3_kernel() {
  __shared__ float s[64 * 101];
  size_t row0 = (size_t)blockIdx.x * 64;
  int tid = threadIdx.x;
  for (int i = tid; i < 6400; i += 256) {
    int r = i / 100, t = i - r * 100;
    s[r * 101 + t] = g_cur2[row0 * 100 + i];
  }
  __syncthreads();
  if (tid < 64) {
    float v = 0.f, sp = 0.f, y1 = 0.f, y2 = 0.f;
    float* row = &s[tid * 101];
#pragma unroll
    for (int t = 0; t < NT; t++) {
      // v = (v*EM)*(1-s) + c  — separate mul/mul/add, XLA association
      v = __fadd_rn(__fmul_rn(__fmul_rn(v, EMC), __fadd_rn(1.0f, -sp)), row[t]);
      sp = (v > 1.0f) ? 1.0f : 0.f;
      float y = __fadd_rn(__fadd_rn(__fmul_rn(A1C, y1), __fmul_rn(A2C, y2)), sp);
      row[t] = y;
      y2 = y1; y1 = y;
    }
  }
  __syncthreads();
  for (int i = tid; i < 6400; i += 256) {
    int r = i / 100, t = i - r * 100;
    g_psp3[row0 * 100 + i] = s[r * 101 + t];
  }
}

// ---------------- kernel 6: GEMM3 + LIF layer 3 -> spikes --------------------
__global__ __launch_bounds__(256) void gemm3_out_kernel(
    const float* __restrict__ W3, const float* __restrict__ b3,
    float* __restrict__ out) {
  __shared__ float Ws[10 * 500];
  __shared__ float cur[1000];
  int b = blockIdx.x;
  int tid = threadIdx.x;
  for (int i = tid; i < 5000; i += 256) Ws[i] = W3[i];
  __syncthreads();
#pragma unroll
  for (int rr = 0; rr < 4; rr++) {
    int idx = tid + 256 * rr;
    if (idx < 1000) {
      int o = idx / 100, t = idx - o * 100;
      const float* p = &g_psp3[(size_t)b * FH * NT + t];
      const float* w = &Ws[o * 500];
      float acc = 0.f;
#pragma unroll 4
      for (int f = 0; f < FH; f++) acc = fmaf(w[f], p[(size_t)f * NT], acc);
      cur[idx] = __fadd_rn(acc, b3[o]);   // bias added after dot, like XLA
    }
  }
  __syncthreads();
  if (tid < 10) {
    float v = 0.f, sp = 0.f;
    const float* c = &cur[tid * 100];
    float* po = &out[((size_t)b * 10 + tid) * NT];
#pragma unroll
    for (int t = 0; t < NT; t++) {
      v = __fadd_rn(__fmul_rn(__fmul_rn(v, EMC), __fadd_rn(1.0f, -sp)), c[t]);
      sp = (v > 1.0f) ? 1.0f : 0.f;
      po[t] = sp;
    }
  }
}

// ---------------- launcher ---------------------------------------------------
extern "C" void kernel_launch(void* const* d_in, const int* in_sizes, int n_in,
                              void* d_out, int out_size) {
  const float *X = nullptr, *W1 = nullptr, *b1 = nullptr, *W2 = nullptr,
              *b2 = nullptr, *W3 = nullptr, *b3 = nullptr;
  // robust mapping by element count (all sizes distinct)
  for (int i = 0; i < n_in; i++) {
    switch (in_sizes[i]) {
      case 20070400: X  = (const float*)d_in[i]; break;  // 256*784*100
      case 784000:   W1 = (const float*)d_in[i]; break;  // 1000*784
      case 1000:     b1 = (const float*)d_in[i]; break;
      case 250000:   W2 = (const float*)d_in[i]; break;  // 500*500
      case 500:      b2 = (const float*)d_in[i]; break;
      case 5000:     W3 = (const float*)d_in[i]; break;  // 10*500
      case 10:       b3 = (const float*)d_in[i]; break;
      default: break;
    }
  }
  float* out = (float*)d_out;

  eps_kernel<<<(NELEM + 255) / 256, 256>>>();
  gemm1_coding_kernel<<<dim3(16, NB), dim3(32, 8)>>>(X, W1, b1);
  iir_kernel<<<(NB * FH) / 64, 256>>>();
  gemm2_kernel<<<dim3(8, NB), dim3(32, 8)>>>(W2, b2);
  lif2_psp3_kernel<<<(NB * FH) / 64, 256>>>();
  gemm3_out_kernel<<<NB, 256>>>(W3, b3, out);
}

// round 4
// speedup vs baseline: 1.1199x; 1.1199x over previous
#include <cuda_runtime.h>
#include <cstdint>
#include <cstddef>

#define NB 256
#define FIN 784
#define FH 500
#define NT 100
#define NELEM (NB*FH*NT)      /* 12,800,000 */

// Filter / neuron constants (python doubles rounded to nearest f32)
#define EMC 0.7788007830714049f
#define A1C 1.1466802242428472f
#define A2C (-0.2865047968601901f)

// ---------------- scratch (device globals: no allocations allowed) ----------
__device__ float g_eps[NELEM];
__device__ float g_psp2[NELEM];
__device__ float g_psp3[NELEM];

// ---------------- JAX threefry-2x32, key = (0, 42) ---------------------------
__device__ __forceinline__ uint32_t rotl32(uint32_t v, int d) {
  return (v << d) | (v >> (32 - d));
}

__device__ __forceinline__ void threefry_0_42(uint32_t x0, uint32_t x1,
                                              uint32_t& o0, uint32_t& o1) {
  const uint32_t ks0 = 0u;
  const uint32_t ks1 = 42u;
  const uint32_t ks2 = 0x1BD11BDAu ^ 0u ^ 42u;
  x0 += ks0; x1 += ks1;
#define TF_R(d) { x0 += x1; x1 = rotl32(x1, d); x1 ^= x0; }
  TF_R(13) TF_R(15) TF_R(26) TF_R(6)
  x0 += ks1; x1 += ks2 + 1u;
  TF_R(17) TF_R(29) TF_R(16) TF_R(24)
  x0 += ks2; x1 += ks0 + 2u;
  TF_R(13) TF_R(15) TF_R(26) TF_R(6)
  x0 += ks0; x1 += ks1 + 3u;
  TF_R(17) TF_R(29) TF_R(16) TF_R(24)
  x0 += ks1; x1 += ks2 + 4u;
  TF_R(13) TF_R(15) TF_R(26) TF_R(6)
  x0 += ks2; x1 += ks0 + 5u;
#undef TF_R
  o0 = x0; o1 = x1;
}

// XLA ErfInv32 polynomial; mul/add kept separate (matches XLA's expansion).
__device__ __forceinline__ float erfinv_xla(float x) {
  float nx2 = __fmul_rn(x, x);
  float w = -log1pf(-nx2);
  float p;
  if (w < 5.0f) {
    w = __fadd_rn(w, -2.5f);
    p = 2.81022636e-08f;
    p = __fadd_rn(3.43273939e-07f, __fmul_rn(p, w));
    p = __fadd_rn(-3.5233877e-06f, __fmul_rn(p, w));
    p = __fadd_rn(-4.39150654e-06f, __fmul_rn(p, w));
    p = __fadd_rn(0.00021858087f, __fmul_rn(p, w));
    p = __fadd_rn(-0.00125372503f, __fmul_rn(p, w));
    p = __fadd_rn(-0.00417768164f, __fmul_rn(p, w));
    p = __fadd_rn(0.246640727f, __fmul_rn(p, w));
    p = __fadd_rn(1.50140941f, __fmul_rn(p, w));
  } else {
    w = __fadd_rn(sqrtf(w), -3.0f);
    p = -0.000200214257f;
    p = __fadd_rn(0.000100950558f, __fmul_rn(p, w));
    p = __fadd_rn(0.00134934322f, __fmul_rn(p, w));
    p = __fadd_rn(-0.00367342844f, __fmul_rn(p, w));
    p = __fadd_rn(0.00573950773f, __fmul_rn(p, w));
    p = __fadd_rn(-0.0076224613f, __fmul_rn(p, w));
    p = __fadd_rn(0.00943887047f, __fmul_rn(p, w));
    p = __fadd_rn(1.00167406f, __fmul_rn(p, w));
    p = __fadd_rn(2.83297682f, __fmul_rn(p, w));
  }
  return __fmul_rn(p, x);
}

__device__ __forceinline__ float bits_to_normal(uint32_t bits) {
  const float lo = -0.99999994039535522461f;
  float f = __fadd_rn(__uint_as_float((bits >> 9) | 0x3f800000u), -1.0f);
  float u = __fadd_rn(__fmul_rn(f, 2.0f), lo);
  u = fmaxf(u, lo);
  return __fmul_rn(1.4142135623730951f, erfinv_xla(u));
}

// ---------------- kernel 1: eps stream (partitionable threefry) --------------
__global__ __launch_bounds__(256) void eps_kernel() {
  uint32_t base = (blockIdx.x * 256u + threadIdx.x) * 4u;
  if (base < NELEM) {
    float o[4];
#pragma unroll
    for (int j = 0; j < 4; j++) {
      uint32_t r0, r1;
      threefry_0_42(0u, base + j, r0, r1);
      o[j] = bits_to_normal(r0 ^ r1);
    }
    *reinterpret_cast<float4*>(g_eps + base) =
        make_float4(o[0], o[1], o[2], o[3]);
  }
}

// ---------------- kernel 2: GEMM1 + relu + coding + IIR -> psp2 --------------
// Block: one b, 32 mu-rows (+ paired 32 lnvar rows) x 128 t (100 real).
// 128 threads, thread tile 4f(x2) x 8t. Epilogue runs the dual-exp IIR
// in-block (each block owns full time rows) and stores psp2 directly.
__global__ __launch_bounds__(128) void gemm1_fused_kernel(
    const float* __restrict__ X, const float* __restrict__ W1,
    const float* __restrict__ b1) {
  __shared__ float pool[6208];          // Xs[32][128] | Wm[32][33] | Wl[32][33]
  float* Xs = pool;
  float* Wm = pool + 4096;
  float* Wl = pool + 5152;
  int b  = blockIdx.y;
  int f0 = blockIdx.x * 32;
  int tid = threadIdx.x;
  int tx = tid & 15;                    // 16 groups x 8t = 128 t
  int ty = tid >> 4;                    // 8 groups x 4f = 32 f
  float accm[4][8] = {{0.f}}, accl[4][8] = {{0.f}};
  const float* Xb = X + (size_t)b * FIN * NT;

#pragma unroll 1
  for (int k0 = 0; k0 < FIN; k0 += 32) {
#pragma unroll
    for (int i = tid; i < 1024; i += 128) {
      int kk = i >> 5, g = i & 31;
      int k = k0 + kk, t = g * 4;
      float4 v = make_float4(0.f, 0.f, 0.f, 0.f);
      if (k < FIN && t < NT)
        v = *reinterpret_cast<const float4*>(Xb + (size_t)k * NT + t);
      *reinterpret_cast<float4*>(Xs + kk * 128 + t) = v;
    }
#pragma unroll
    for (int i = tid; i < 1024; i += 128) {
      int fi = i >> 5, kk = i & 31;
      int f = f0 + fi, k = k0 + kk;
      bool ok = (f < FH) && (k < FIN);
      Wm[fi * 33 + kk] = ok ? W1[(size_t)f * FIN + k] : 0.f;
      Wl[fi * 33 + kk] = ok ? W1[(size_t)(f + FH) * FIN + k] : 0.f;
    }
    __syncthreads();
#pragma unroll
    for (int kk = 0; kk < 32; kk++) {
      float4 a0 = *reinterpret_cast<const float4*>(Xs + kk * 128 + tx * 8);
      float4 a1 = *reinterpret_cast<const float4*>(Xs + kk * 128 + tx * 8 + 4);
      float xa[8] = {a0.x, a0.y, a0.z, a0.w, a1.x, a1.y, a1.z, a1.w};
#pragma unroll
      for (int j = 0; j < 4; j++) {
        float wm = Wm[(ty * 4 + j) * 33 + kk];
        float wl = Wl[(ty * 4 + j) * 33 + kk];
#pragma unroll
        for (int r = 0; r < 8; r++) {
          accm[j][r] = fmaf(wm, xa[r], accm[j][r]);
          accl[j][r] = fmaf(wl, xa[r], accl[j][r]);
        }
      }
    }
    __syncthreads();
  }

  // ---- epilogue: coding into smem rows (overlay pool), IIR, store ----
  float* rows = pool;                   // [32][101]
#pragma unroll
  for (int j = 0; j < 4; j++) {
    int fi = ty * 4 + j, f = f0 + fi;
#pragma unroll
    for (int r = 0; r < 8; r++) {
      int t = tx * 8 + r;
      if (t < NT) {
        float val = 0.f;
        if (f < FH) {
          float mu = fmaxf(__fadd_rn(accm[j][r], b1[f]), 0.f);
          float lv = fmaxf(__fadd_rn(accl[j][r], b1[f + FH]), 0.f);
          size_t idx = ((size_t)b * FH + f) * NT + t;
          float sg = expf(__fmul_rn(0.5f, lv));
          val = __fadd_rn(mu, __fmul_rn(g_eps[idx], sg));
        }
        rows[fi * 101 + t] = val;
      }
    }
  }
  __syncthreads();
  if (tid < 32) {
    float y1 = 0.f, y2 = 0.f;
    float* row = rows + tid * 101;
#pragma unroll
    for (int t = 0; t < NT; t++) {
      float y = __fadd_rn(__fadd_rn(__fmul_rn(A1C, y1), __fmul_rn(A2C, y2)),
                          row[t]);
      row[t] = y;
      y2 = y1; y1 = y;
    }
  }
  __syncthreads();
  for (int i = tid; i < 3200; i += 128) {
    int r = i / 100, t = i - r * 100;
    int f = f0 + r;
    if (f < FH)
      g_psp2[((size_t)b * FH + f) * NT + t] = rows[r * 101 + t];
  }
}

// ---------------- kernel 3: GEMM2 + LIF + IIR -> psp3 ------------------------
// Block: one b, 64 f-rows x 128 t (100 real). 128 threads, thread 8f x 8t.
__global__ __launch_bounds__(128) void gemm2_fused_kernel(
    const float* __restrict__ W2, const float* __restrict__ b2) {
  __shared__ float pool[6464];          // Xs[32][128] | Ws[64][33]; rows[64][101]
  float* Xs = pool;
  float* Ws = pool + 4096;
  int b  = blockIdx.y;
  int f0 = blockIdx.x * 64;
  int tid = threadIdx.x;
  int tx = tid & 15;
  int ty = tid >> 4;                    // 8 groups x 8f = 64 f
  float acc[8][8] = {{0.f}};
  const float* Pb = g_psp2 + (size_t)b * FH * NT;

#pragma unroll 1
  for (int k0 = 0; k0 < FH; k0 += 32) {
#pragma unroll
    for (int i = tid; i < 1024; i += 128) {
      int kk = i >> 5, g = i & 31;
      int k = k0 + kk, t = g * 4;
      float4 v = make_float4(0.f, 0.f, 0.f, 0.f);
      if (k < FH && t < NT)
        v = *reinterpret_cast<const float4*>(Pb + (size_t)k * NT + t);
      *reinterpret_cast<float4*>(Xs + kk * 128 + t) = v;
    }
#pragma unroll
    for (int i = tid; i < 2048; i += 128) {
      int fi = i >> 5, kk = i & 31;
      int f = f0 + fi, k = k0 + kk;
      Ws[fi * 33 + kk] = (f < FH && k < FH) ? W2[(size_t)f * FH + k] : 0.f;
    }
    __syncthreads();
#pragma unroll
    for (int kk = 0; kk < 32; kk++) {
      float4 a0 = *reinterpret_cast<const float4*>(Xs + kk * 128 + tx * 8);
      float4 a1 = *reinterpret_cast<const float4*>(Xs + kk * 128 + tx * 8 + 4);
      float xa[8] = {a0.x, a0.y, a0.z, a0.w, a1.x, a1.y, a1.z, a1.w};
#pragma unroll
      for (int j = 0; j < 8; j++) {
        float w = Ws[(ty * 8 + j) * 33 + kk];
#pragma unroll
        for (int r = 0; r < 8; r++) acc[j][r] = fmaf(w, xa[r], acc[j][r]);
      }
    }
    __syncthreads();
  }

  // ---- epilogue: bias, LIF spikes, second IIR, store psp3 ----
  float* rows = pool;                   // [64][101]
#pragma unroll
  for (int j = 0; j < 8; j++) {
    int fi = ty * 8 + j, f = f0 + fi;
#pragma unroll
    for (int r = 0; r < 8; r++) {
      int t = tx * 8 + r;
      if (t < NT)
        rows[fi * 101 + t] = (f < FH) ? __fadd_rn(acc[j][r], b2[f]) : 0.f;
    }
  }
  __syncthreads();
  if (tid < 64) {
    float v = 0.f, sp = 0.f, y1 = 0.f, y2 = 0.f;
    float* row = rows + tid * 101;
#pragma unroll
    for (int t = 0; t < NT; t++) {
      v = __fadd_rn(__fmul_rn(__fmul_rn(v, EMC), __fadd_rn(1.0f, -sp)), row[t]);
      sp = (v > 1.0f) ? 1.0f : 0.f;
      float y = __fadd_rn(__fadd_rn(__fmul_rn(A1C, y1), __fmul_rn(A2C, y2)), sp);
      row[t] = y;
      y2 = y1; y1 = y;
    }
  }
  __syncthreads();
  for (int i = tid; i < 6400; i += 128) {
    int r = i / 100, t = i - r * 100;
    int f = f0 + r;
    if (f < FH)
      g_psp3[((size_t)b * FH + f) * NT + t] = rows[r * 101 + t];
  }
}

// ---------------- kernel 4: GEMM3 + LIF layer 3 -> spikes --------------------
__global__ __launch_bounds__(256) void gemm3_out_kernel(
    const float* __restrict__ W3, const float* __restrict__ b3,
    float* __restrict__ out) {
  __shared__ float Ws[10 * 500];
  __shared__ float cur[1000];
  int b = blockIdx.x;
  int tid = threadIdx.x;
  for (int i = tid; i < 5000; i += 256) Ws[i] = W3[i];
  __syncthreads();
#pragma unroll
  for (int rr = 0; rr < 4; rr++) {
    int idx = tid + 256 * rr;
    if (idx < 1000) {
      int o = idx / 100, t = idx - o * 100;
      const float* p = &g_psp3[(size_t)b * FH * NT + t];
      const float* w = &Ws[o * 500];
      float acc = 0.f;
#pragma unroll 4
      for (int f = 0; f < FH; f++) acc = fmaf(w[f], p[(size_t)f * NT], acc);
      cur[idx] = __fadd_rn(acc, b3[o]);
    }
  }
  __syncthreads();
  if (tid < 10) {
    float v = 0.f, sp = 0.f;
    const float* c = &cur[tid * 100];
    float* po = &out[((size_t)b * 10 + tid) * NT];
#pragma unroll
    for (int t = 0; t < NT; t++) {
      v = __fadd_rn(__fmul_rn(__fmul_rn(v, EMC), __fadd_rn(1.0f, -sp)), c[t]);
      sp = (v > 1.0f) ? 1.0f : 0.f;
      po[t] = sp;
    }
  }
}

// ---------------- launcher ---------------------------------------------------
extern "C" void kernel_launch(void* const* d_in, const int* in_sizes, int n_in,
                              void* d_out, int out_size) {
  const float *X = nullptr, *W1 = nullptr, *b1 = nullptr, *W2 = nullptr,
              *b2 = nullptr, *W3 = nullptr, *b3 = nullptr;
  for (int i = 0; i < n_in; i++) {
    switch (in_sizes[i]) {
      case 20070400: X  = (const float*)d_in[i]; break;  // 256*784*100
      case 784000:   W1 = (const float*)d_in[i]; break;  // 1000*784
      case 1000:     b1 = (const float*)d_in[i]; break;
      case 250000:   W2 = (const float*)d_in[i]; break;  // 500*500
      case 500:      b2 = (const float*)d_in[i]; break;
      case 5000:     W3 = (const float*)d_in[i]; break;  // 10*500
      case 10:       b3 = (const float*)d_in[i]; break;
      default: break;
    }
  }
  float* out = (float*)d_out;

  eps_kernel<<<NELEM / 1024, 256>>>();
  gemm1_fused_kernel<<<dim3(16, NB), 128>>>(X, W1, b1);
  gemm2_fused_kernel<<<dim3(8, NB), 128>>>(W2, b2);
  gemm3_out_kernel<<<NB, 256>>>(W3, b3, out);
}

// round 5
// speedup vs baseline: 1.1744x; 1.0487x over previous
#include <cuda_runtime.h>
#include <cstdint>
#include <cstddef>

#define NB 256
#define FIN 784
#define FH 500
#define NT 100
#define J 25600                 /* NB*NT flattened column dim */
#define NELEM (FH*J)            /* 12,800,000 */

#define EMC 0.7788007830714049f
#define A1C 1.1466802242428472f
#define A2C (-0.2865047968601901f)

// ---------------- scratch (device globals) -----------------------------------
__device__ float g_eps[NELEM];   // [f][J]
__device__ float g_psp2[NELEM];  // coding -> (IIR in place) psp2, [f][J]
__device__ float g_cur2[NELEM];  // [f][J]
__device__ float g_psp3[NELEM];  // [f][J]
__device__ float g_cur3[10 * J]; // [o][J]

// ---------------- JAX threefry-2x32, key = (0, 42) ---------------------------
__device__ __forceinline__ uint32_t rotl32(uint32_t v, int d) {
  return (v << d) | (v >> (32 - d));
}

__device__ __forceinline__ void threefry_0_42(uint32_t x0, uint32_t x1,
                                              uint32_t& o0, uint32_t& o1) {
  const uint32_t ks1 = 42u;
  const uint32_t ks2 = 0x1BD11BDAu ^ 42u;
  x1 += ks1;
#define TF_R(d) { x0 += x1; x1 = rotl32(x1, d); x1 ^= x0; }
  TF_R(13) TF_R(15) TF_R(26) TF_R(6)
  x0 += ks1; x1 += ks2 + 1u;
  TF_R(17) TF_R(29) TF_R(16) TF_R(24)
  x0 += ks2; x1 += 2u;
  TF_R(13) TF_R(15) TF_R(26) TF_R(6)
  x0 += 0u; x1 += ks1 + 3u;
  TF_R(17) TF_R(29) TF_R(16) TF_R(24)
  x0 += ks1; x1 += ks2 + 4u;
  TF_R(13) TF_R(15) TF_R(26) TF_R(6)
  x0 += ks2; x1 += 5u;
#undef TF_R
  o0 = x0; o1 = x1;
}

__device__ __forceinline__ float erfinv_xla(float x) {
  float nx2 = __fmul_rn(x, x);
  float w = -log1pf(-nx2);
  float p;
  if (w < 5.0f) {
    w = __fadd_rn(w, -2.5f);
    p = 2.81022636e-08f;
    p = __fadd_rn(3.43273939e-07f, __fmul_rn(p, w));
    p = __fadd_rn(-3.5233877e-06f, __fmul_rn(p, w));
    p = __fadd_rn(-4.39150654e-06f, __fmul_rn(p, w));
    p = __fadd_rn(0.00021858087f, __fmul_rn(p, w));
    p = __fadd_rn(-0.00125372503f, __fmul_rn(p, w));
    p = __fadd_rn(-0.00417768164f, __fmul_rn(p, w));
    p = __fadd_rn(0.246640727f, __fmul_rn(p, w));
    p = __fadd_rn(1.50140941f, __fmul_rn(p, w));
  } else {
    w = __fadd_rn(sqrtf(w), -3.0f);
    p = -0.000200214257f;
    p = __fadd_rn(0.000100950558f, __fmul_rn(p, w));
    p = __fadd_rn(0.00134934322f, __fmul_rn(p, w));
    p = __fadd_rn(-0.00367342844f, __fmul_rn(p, w));
    p = __fadd_rn(0.00573950773f, __fmul_rn(p, w));
    p = __fadd_rn(-0.0076224613f, __fmul_rn(p, w));
    p = __fadd_rn(0.00943887047f, __fmul_rn(p, w));
    p = __fadd_rn(1.00167406f, __fmul_rn(p, w));
    p = __fadd_rn(2.83297682f, __fmul_rn(p, w));
  }
  return __fmul_rn(p, x);
}

__device__ __forceinline__ float bits_to_normal(uint32_t bits) {
  const float lo = -0.99999994039535522461f;
  float f = __fadd_rn(__uint_as_float((bits >> 9) | 0x3f800000u), -1.0f);
  float u = __fadd_rn(__fmul_rn(f, 2.0f), lo);
  u = fmaxf(u, lo);
  return __fmul_rn(1.4142135623730951f, erfinv_xla(u));
}

// ---------------- kernel 1: eps in [f][J] layout ------------------------------
// Logical element (b,f,t) has threefry counter b*50000+f*100+t (row-major in
// the reference's (B,F,T) shape); stored at g_eps[f*J + b*100 + t].
__global__ __launch_bounds__(256) void eps_kernel() {
  uint32_t base = (blockIdx.x * 256u + threadIdx.x) * 4u;
  if (base < NELEM) {
    float o[4];
#pragma unroll
    for (int jj = 0; jj < 4; jj++) {
      uint32_t idx = base + jj;
      uint32_t f = idx / J;
      uint32_t rem = idx - f * J;
      uint32_t b = rem / NT;
      uint32_t t = rem - b * NT;
      uint32_t r0, r1;
      threefry_0_42(0u, b * 50000u + f * 100u + t, r0, r1);
      o[jj] = bits_to_normal(r0 ^ r1);
    }
    *reinterpret_cast<float4*>(g_eps + base) =
        make_float4(o[0], o[1], o[2], o[3]);
  }
}

// ---------------- kernel 2: GEMM1 + relu + coding -> g_psp2[f][J] -------------
// Block tile 64f x 256j; f rows = 32 mu (f0..f0+31) + 32 lnvar (500+f0..).
// 128 threads, thread tile 8f x 16j (split 4+4 / 4x4).
__global__ __launch_bounds__(128, 2) void gemm1_kernel(
    const float* __restrict__ X, const float* __restrict__ W1,
    const float* __restrict__ b1) {
  __shared__ float Xs[32][256];
  __shared__ float Ws[32][68];
  int j0 = blockIdx.x * 256;
  int f0 = blockIdx.y * 32;
  int tid = threadIdx.x;
  int tx = tid & 15, ty = tid >> 4;
  // column base pointers for gather staging (input X is [b][784][100])
  int ja = j0 + tid, jb = j0 + tid + 128;
  const float* pxa = X + (size_t)(ja / NT) * (FIN * NT) + (ja % NT);
  const float* pxb = X + (size_t)(jb / NT) * (FIN * NT) + (jb % NT);

  float acc[8][16];
#pragma unroll
  for (int i = 0; i < 8; i++)
#pragma unroll
    for (int r = 0; r < 16; r++) acc[i][r] = 0.f;

  for (int k0 = 0; k0 < 800; k0 += 32) {
    // stage X columns (2 per thread, 32 k each)
#pragma unroll
    for (int kk = 0; kk < 32; kk++) {
      int k = k0 + kk;
      Xs[kk][tid]       = (k < FIN) ? pxa[(size_t)k * NT] : 0.f;
      Xs[kk][tid + 128] = (k < FIN) ? pxb[(size_t)k * NT] : 0.f;
    }
    // stage W: 64 rows (32 mu + 32 lv) x 32 k, transposed into Ws[kk][fi]
#pragma unroll
    for (int s = 0; s < 4; s++) {
      int i = tid + s * 128;
      int fi = i >> 3, kq = i & 7;
      int fl = (fi < 32) ? (f0 + fi) : (f0 + fi - 32);
      int f  = (fi < 32) ? fl : (fl + FH);
      int k = k0 + kq * 4;
      float4 w = make_float4(0.f, 0.f, 0.f, 0.f);
      if (fl < FH && k < FIN)
        w = *reinterpret_cast<const float4*>(W1 + (size_t)f * FIN + k);
      Ws[kq * 4 + 0][fi] = w.x;
      Ws[kq * 4 + 1][fi] = w.y;
      Ws[kq * 4 + 2][fi] = w.z;
      Ws[kq * 4 + 3][fi] = w.w;
    }
    __syncthreads();
#pragma unroll 8
    for (int kk = 0; kk < 32; kk++) {
      float4 x0 = *reinterpret_cast<const float4*>(&Xs[kk][tx * 4]);
      float4 x1 = *reinterpret_cast<const float4*>(&Xs[kk][tx * 4 + 64]);
      float4 x2 = *reinterpret_cast<const float4*>(&Xs[kk][tx * 4 + 128]);
      float4 x3 = *reinterpret_cast<const float4*>(&Xs[kk][tx * 4 + 192]);
      float4 a0 = *reinterpret_cast<const float4*>(&Ws[kk][ty * 4]);
      float4 a1 = *reinterpret_cast<const float4*>(&Ws[kk][ty * 4 + 32]);
      float av[8] = {a0.x, a0.y, a0.z, a0.w, a1.x, a1.y, a1.z, a1.w};
      float bv[16] = {x0.x, x0.y, x0.z, x0.w, x1.x, x1.y, x1.z, x1.w,
                      x2.x, x2.y, x2.z, x2.w, x3.x, x3.y, x3.z, x3.w};
#pragma unroll
      for (int i = 0; i < 8; i++)
#pragma unroll
        for (int r = 0; r < 16; r++)
          acc[i][r] = fmaf(av[i], bv[r], acc[i][r]);
    }
    __syncthreads();
  }

  // epilogue: acc[c] = mu row f0+ty*4+c, acc[4+c] = lnvar row (+500 in W)
#pragma unroll
  for (int c = 0; c < 4; c++) {
    int f = f0 + ty * 4 + c;
    if (f >= FH) continue;
    float bm = b1[f], bl = b1[f + FH];
#pragma unroll
    for (int q = 0; q < 4; q++) {
      int j = j0 + q * 64 + tx * 4;
      float4 e = *reinterpret_cast<const float4*>(g_eps + (size_t)f * J + j);
      float ev[4] = {e.x, e.y, e.z, e.w};
      float o[4];
#pragma unroll
      for (int r = 0; r < 4; r++) {
        float mu = fmaxf(__fadd_rn(acc[c][q * 4 + r], bm), 0.f);
        float lv = fmaxf(__fadd_rn(acc[4 + c][q * 4 + r], bl), 0.f);
        float sg = expf(__fmul_rn(0.5f, lv));
        o[r] = __fadd_rn(mu, __fmul_rn(ev[r], sg));
      }
      *reinterpret_cast<float4*>(g_psp2 + (size_t)f * J + j) =
          make_float4(o[0], o[1], o[2], o[3]);
    }
  }
}

// ---------------- kernel 3: dual-exp IIR in place on g_psp2 ------------------
// Row (f,b) is 100 contiguous floats at offset (f*256+b)*100 == rid*100.
__global__ __launch_bounds__(256) void iir_kernel() {
  __shared__ float s[64 * 101];
  size_t row0 = (size_t)blockIdx.x * 64;
  int tid = threadIdx.x;
  for (int i = tid; i < 6400; i += 256) {
    int r = i / 100, t = i - r * 100;
    s[r * 101 + t] = g_psp2[row0 * 100 + i];
  }
  __syncthreads();
  if (tid < 64) {
    float y1 = 0.f, y2 = 0.f;
    float* row = s + tid * 101;
#pragma unroll
    for (int t = 0; t < NT; t++) {
      float y = __fadd_rn(__fadd_rn(__fmul_rn(A1C, y1), __fmul_rn(A2C, y2)),
                          row[t]);
      row[t] = y;
      y2 = y1; y1 = y;
    }
  }
  __syncthreads();
  for (int i = tid; i < 6400; i += 256) {
    int r = i / 100, t = i - r * 100;
    g_psp2[row0 * 100 + i] = s[r * 101 + t];
  }
}

// ---------------- kernel 4: GEMM2 -> g_cur2[f][J] ----------------------------
// Block tile 64f x 256j, 128 threads, thread 8f x 16j.
__global__ __launch_bounds__(128, 2) void gemm2_kernel(
    const float* __restrict__ W2, const float* __restrict__ b2) {
  __shared__ float Xs[32][256];
  __shared__ float Ws[32][68];
  int j0 = blockIdx.x * 256;
  int f0 = blockIdx.y * 64;
  int tid = threadIdx.x;
  int tx = tid & 15, ty = tid >> 4;

  float acc[8][16];
#pragma unroll
  for (int i = 0; i < 8; i++)
#pragma unroll
    for (int r = 0; r < 16; r++) acc[i][r] = 0.f;

  for (int k0 = 0; k0 < 512; k0 += 32) {
    // stage X: straight [f][J] tile copy, float4
#pragma unroll
    for (int s = 0; s < 16; s++) {
      int i = tid + s * 128;          // 0..2047 float4s
      int kk = i >> 6, c4 = i & 63;
      int k = k0 + kk;
      float4 v = make_float4(0.f, 0.f, 0.f, 0.f);
      if (k < FH)
        v = *reinterpret_cast<const float4*>(g_psp2 + (size_t)k * J + j0 + c4 * 4);
      *reinterpret_cast<float4*>(&Xs[kk][c4 * 4]) = v;
    }
#pragma unroll
    for (int s = 0; s < 4; s++) {
      int i = tid + s * 128;
      int fi = i >> 3, kq = i & 7;
      int f = f0 + fi;
      int k = k0 + kq * 4;
      float4 w = make_float4(0.f, 0.f, 0.f, 0.f);
      if (f < FH && k < FH)
        w = *reinterpret_cast<const float4*>(W2 + (size_t)f * FH + k);
      Ws[kq * 4 + 0][fi] = w.x;
      Ws[kq * 4 + 1][fi] = w.y;
      Ws[kq * 4 + 2][fi] = w.z;
      Ws[kq * 4 + 3][fi] = w.w;
    }
    __syncthreads();
#pragma unroll 8
    for (int kk = 0; kk < 32; kk++) {
      float4 x0 = *reinterpret_cast<const float4*>(&Xs[kk][tx * 4]);
      float4 x1 = *reinterpret_cast<const float4*>(&Xs[kk][tx * 4 + 64]);
      float4 x2 = *reinterpret_cast<const float4*>(&Xs[kk][tx * 4 + 128]);
      float4 x3 = *reinterpret_cast<const float4*>(&Xs[kk][tx * 4 + 192]);
      float4 a0 = *reinterpret_cast<const float4*>(&Ws[kk][ty * 4]);
      float4 a1 = *reinterpret_cast<const float4*>(&Ws[kk][ty * 4 + 32]);
      float av[8] = {a0.x, a0.y, a0.z, a0.w, a1.x, a1.y, a1.z, a1.w};
      float bv[16] = {x0.x, x0.y, x0.z, x0.w, x1.x, x1.y, x1.z, x1.w,
                      x2.x, x2.y, x2.z, x2.w, x3.x, x3.y, x3.z, x3.w};
#pragma unroll
      for (int i = 0; i < 8; i++)
#pragma unroll
        for (int r = 0; r < 16; r++)
          acc[i][r] = fmaf(av[i], bv[r], acc[i][r]);
    }
    __syncthreads();
  }

#pragma unroll
  for (int g = 0; g < 2; g++) {
#pragma unroll
    for (int c = 0; c < 4; c++) {
      int f = f0 + g * 32 + ty * 4 + c;
      if (f >= FH) continue;
      float bb = b2[f];
#pragma unroll
      for (int q = 0; q < 4; q++) {
        int j = j0 + q * 64 + tx * 4;
        float o[4];
#pragma unroll
        for (int r = 0; r < 4; r++)
          o[r] = __fadd_rn(acc[g * 4 + c][q * 4 + r], bb);
        *reinterpret_cast<float4*>(g_cur2 + (size_t)f * J + j) =
            make_float4(o[0], o[1], o[2], o[3]);
      }
    }
  }
}

// ---------------- kernel 5: LIF + second IIR: g_cur2 -> g_psp3 ---------------
__global__ __launch_bounds__(256) void lifiir_kernel() {
  __shared__ float s[64 * 101];
  size_t row0 = (size_t)blockIdx.x * 64;
  int tid = threadIdx.x;
  for (int i = tid; i < 6400; i += 256) {
    int r = i / 100, t = i - r * 100;
    s[r * 101 + t] = g_cur2[row0 * 100 + i];
  }
  __syncthreads();
  if (tid < 64) {
    float v = 0.f, sp = 0.f, y1 = 0.f, y2 = 0.f;
    float* row = s + tid * 101;
#pragma unroll
    for (int t = 0; t < NT; t++) {
      v = __fadd_rn(__fmul_rn(__fmul_rn(v, EMC), __fadd_rn(1.0f, -sp)), row[t]);
      sp = (v > 1.0f) ? 1.0f : 0.f;
      float y = __fadd_rn(__fadd_rn(__fmul_rn(A1C, y1), __fmul_rn(A2C, y2)), sp);
      row[t] = y;
      y2 = y1; y1 = y;
    }
  }
  __syncthreads();
  for (int i = tid; i < 6400; i += 256) {
    int r = i / 100, t = i - r * 100;
    g_psp3[row0 * 100 + i] = s[r * 101 + t];
  }
}

// ---------------- kernel 6: GEMM3 -> g_cur3[o][J] ----------------------------
__global__ __launch_bounds__(128) void gemm3_kernel(
    const float* __restrict__ W3, const float* __restrict__ b3) {
  __shared__ float Ws[10 * FH];
  int j = blockIdx.x * 128 + threadIdx.x;
  for (int i = threadIdx.x; i < 10 * FH; i += 128) Ws[i] = W3[i];
  __syncthreads();
  float acc[10];
#pragma unroll
  for (int o = 0; o < 10; o++) acc[o] = 0.f;
  const float* p = g_psp3 + j;
#pragma unroll 8
  for (int k = 0; k < FH; k++) {
    float x = p[(size_t)k * J];
#pragma unroll
    for (int o = 0; o < 10; o++) acc[o] = fmaf(Ws[o * FH + k], x, acc[o]);
  }
#pragma unroll
  for (int o = 0; o < 10; o++)
    g_cur3[(size_t)o * J + j] = __fadd_rn(acc[o], b3[o]);
}

// ---------------- kernel 7: LIF layer 3 -> out[b][o][t] ----------------------
__global__ __launch_bounds__(256) void lif3_out_kernel(float* __restrict__ out) {
  __shared__ float s[64 * 101];
  int rid0 = blockIdx.x * 64;     // rid = o*256 + b
  int tid = threadIdx.x;
  for (int i = tid; i < 6400; i += 256) {
    int r = i / 100, t = i - r * 100;
    s[r * 101 + t] = g_cur3[(size_t)rid0 * 100 + i];
  }
  __syncthreads();
  if (tid < 64) {
    int rid = rid0 + tid;
    int o = rid >> 8, b = rid & 255;
    float* po = out + ((size_t)b * 10 + o) * NT;
    const float* row = s + tid * 101;
    float v = 0.f, sp = 0.f;
#pragma unroll
    for (int t = 0; t < NT; t++) {
      v = __fadd_rn(__fmul_rn(__fmul_rn(v, EMC), __fadd_rn(1.0f, -sp)), row[t]);
      sp = (v > 1.0f) ? 1.0f : 0.f;
      po[t] = sp;
    }
  }
}

// ---------------- launcher ---------------------------------------------------
extern "C" void kernel_launch(void* const* d_in, const int* in_sizes, int n_in,
                              void* d_out, int out_size) {
  const float *X = nullptr, *W1 = nullptr, *b1 = nullptr, *W2 = nullptr,
              *b2 = nullptr, *W3 = nullptr, *b3 = nullptr;
  for (int i = 0; i < n_in; i++) {
    switch (in_sizes[i]) {
      case 20070400: X  = (const float*)d_in[i]; break;  // 256*784*100
      case 784000:   W1 = (const float*)d_in[i]; break;  // 1000*784
      case 1000:     b1 = (const float*)d_in[i]; break;
      case 250000:   W2 = (const float*)d_in[i]; break;  // 500*500
      case 500:      b2 = (const float*)d_in[i]; break;
      case 5000:     W3 = (const float*)d_in[i]; break;  // 10*500
      case 10:       b3 = (const float*)d_in[i]; break;
      default: break;
    }
  }
  float* out = (float*)d_out;

  eps_kernel<<<NELEM / 1024, 256>>>();
  gemm1_kernel<<<dim3(100, 16), 128>>>(X, W1, b1);
  iir_kernel<<<2000, 256>>>();
  gemm2_kernel<<<dim3(100, 8), 128>>>(W2, b2);
  lifiir_kernel<<<2000, 256>>>();
  gemm3_kernel<<<J / 128, 128>>>(W3, b3);
  lif3_out_kernel<<<40, 256>>>(out);
}

// round 6
// speedup vs baseline: 1.7361x; 1.4783x over previous
#include <cuda_runtime.h>
#include <cstdint>
#include <cstddef>

#define NB 256
#define FIN 784
#define FH 500
#define NT 100
#define J 25600                 /* NB*NT flattened column dim */
#define NELEM (FH*J)            /* 12,800,000 */

#define EMC 0.7788007830714049f
#define A1C 1.1466802242428472f
#define A2C (-0.2865047968601901f)

// ---------------- scratch (device globals) -----------------------------------
__device__ float g_psp2[NELEM];  // coding -> (IIR in place) psp2, [f][J]
__device__ float g_cur2[NELEM];  // [f][J]
__device__ float g_psp3[NELEM];  // [f][J]
__device__ float g_cur3[10 * J]; // [o][J]

// ---------------- JAX threefry-2x32, key = (0, 42) ---------------------------
__device__ __forceinline__ uint32_t rotl32(uint32_t v, int d) {
  return (v << d) | (v >> (32 - d));
}

__device__ __forceinline__ void threefry_0_42(uint32_t x0, uint32_t x1,
                                              uint32_t& o0, uint32_t& o1) {
  const uint32_t ks1 = 42u;
  const uint32_t ks2 = 0x1BD11BDAu ^ 42u;
  x1 += ks1;
#define TF_R(d) { x0 += x1; x1 = rotl32(x1, d); x1 ^= x0; }
  TF_R(13) TF_R(15) TF_R(26) TF_R(6)
  x0 += ks1; x1 += ks2 + 1u;
  TF_R(17) TF_R(29) TF_R(16) TF_R(24)
  x0 += ks2; x1 += 2u;
  TF_R(13) TF_R(15) TF_R(26) TF_R(6)
  x0 += 0u; x1 += ks1 + 3u;
  TF_R(17) TF_R(29) TF_R(16) TF_R(24)
  x0 += ks1; x1 += ks2 + 4u;
  TF_R(13) TF_R(15) TF_R(26) TF_R(6)
  x0 += ks2; x1 += 5u;
#undef TF_R
  o0 = x0; o1 = x1;
}

__device__ __forceinline__ float erfinv_xla(float x) {
  float nx2 = __fmul_rn(x, x);
  float w = -log1pf(-nx2);
  float p;
  if (w < 5.0f) {
    w = __fadd_rn(w, -2.5f);
    p = 2.81022636e-08f;
    p = __fadd_rn(3.43273939e-07f, __fmul_rn(p, w));
    p = __fadd_rn(-3.5233877e-06f, __fmul_rn(p, w));
    p = __fadd_rn(-4.39150654e-06f, __fmul_rn(p, w));
    p = __fadd_rn(0.00021858087f, __fmul_rn(p, w));
    p = __fadd_rn(-0.00125372503f, __fmul_rn(p, w));
    p = __fadd_rn(-0.00417768164f, __fmul_rn(p, w));
    p = __fadd_rn(0.246640727f, __fmul_rn(p, w));
    p = __fadd_rn(1.50140941f, __fmul_rn(p, w));
  } else {
    w = __fadd_rn(sqrtf(w), -3.0f);
    p = -0.000200214257f;
    p = __fadd_rn(0.000100950558f, __fmul_rn(p, w));
    p = __fadd_rn(0.00134934322f, __fmul_rn(p, w));
    p = __fadd_rn(-0.00367342844f, __fmul_rn(p, w));
    p = __fadd_rn(0.00573950773f, __fmul_rn(p, w));
    p = __fadd_rn(-0.0076224613f, __fmul_rn(p, w));
    p = __fadd_rn(0.00943887047f, __fmul_rn(p, w));
    p = __fadd_rn(1.00167406f, __fmul_rn(p, w));
    p = __fadd_rn(2.83297682f, __fmul_rn(p, w));
  }
  return __fmul_rn(p, x);
}

__device__ __forceinline__ float eps_at(uint32_t ctr) {
  uint32_t r0, r1;
  threefry_0_42(0u, ctr, r0, r1);
  uint32_t bits = r0 ^ r1;
  const float lo = -0.99999994039535522461f;
  float f = __fadd_rn(__uint_as_float((bits >> 9) | 0x3f800000u), -1.0f);
  float u = __fadd_rn(__fmul_rn(f, 2.0f), lo);
  u = fmaxf(u, lo);
  return __fmul_rn(1.4142135623730951f, erfinv_xla(u));
}

// ---------------- kernel 1: GEMM1 + relu + coding(+eps) -> g_psp2[f][J] ------
// Block tile: 128 M-rows (64 mu + 64 lv, same f range) x 128 j. 256 threads,
// thread tile 8x8 (4 mu rows + their 4 paired lv rows; j split 4+4).
__global__ __launch_bounds__(256, 2) void gemm1_kernel(
    const float* __restrict__ X, const float* __restrict__ W1,
    const float* __restrict__ b1) {
  __shared__ float Xs[16][128];
  __shared__ float Ws[16][132];
  int j0 = blockIdx.x * 128;
  int f0 = blockIdx.y * 64;
  int tid = threadIdx.x;
  int tx = tid & 15, ty = tid >> 4;

  // staging identities
  int jj_s = tid & 127;                  // X stage column
  int kh   = tid >> 7;                   // 0/1 -> which 8 k's
  int ja = j0 + jj_s;
  const float* pxa = X + (size_t)(ja / NT) * (FIN * NT) + (ja % NT);
  int fi_s = tid & 127;                  // W stage row
  int kq   = tid >> 7;                   // 0/1
  int flog = f0 + (fi_s & 63);
  int wrow = (fi_s < 64) ? flog : (flog + FH);
  bool wok = (flog < FH);

  float acc[8][8];
#pragma unroll
  for (int i = 0; i < 8; i++)
#pragma unroll
    for (int r = 0; r < 8; r++) acc[i][r] = 0.f;

#pragma unroll 1
  for (int k0 = 0; k0 < FIN; k0 += 16) {   // 49 exact chunks
#pragma unroll
    for (int m = 0; m < 8; m++) {
      int k = k0 + kh * 8 + m;
      Xs[kh * 8 + m][jj_s] = pxa[(size_t)k * NT];
    }
#pragma unroll
    for (int q = 0; q < 2; q++) {
      int kb = k0 + kq * 8 + q * 4;
      float4 w = make_float4(0.f, 0.f, 0.f, 0.f);
      if (wok) w = *reinterpret_cast<const float4*>(W1 + (size_t)wrow * FIN + kb);
      Ws[kq * 8 + q * 4 + 0][fi_s] = w.x;
      Ws[kq * 8 + q * 4 + 1][fi_s] = w.y;
      Ws[kq * 8 + q * 4 + 2][fi_s] = w.z;
      Ws[kq * 8 + q * 4 + 3][fi_s] = w.w;
    }
    __syncthreads();
#pragma unroll
    for (int kk = 0; kk < 16; kk++) {
      float4 a0 = *reinterpret_cast<const float4*>(&Ws[kk][ty * 4]);
      float4 a1 = *reinterpret_cast<const float4*>(&Ws[kk][ty * 4 + 64]);
      float4 b0 = *reinterpret_cast<const float4*>(&Xs[kk][tx * 4]);
      float4 b1v = *reinterpret_cast<const float4*>(&Xs[kk][tx * 4 + 64]);
      float av[8] = {a0.x, a0.y, a0.z, a0.w, a1.x, a1.y, a1.z, a1.w};
      float bv[8] = {b0.x, b0.y, b0.z, b0.w, b1v.x, b1v.y, b1v.z, b1v.w};
#pragma unroll
      for (int i = 0; i < 8; i++)
#pragma unroll
        for (int r = 0; r < 8; r++)
          acc[i][r] = fmaf(av[i], bv[r], acc[i][r]);
    }
    __syncthreads();
  }

  // epilogue: acc[i] (i<4) = mu row f0+ty*4+i; acc[i+4] = paired lnvar row.
#pragma unroll
  for (int i = 0; i < 4; i++) {
    int f = f0 + ty * 4 + i;
    if (f >= FH) continue;
    float bm = b1[f], bl = b1[f + FH];
#pragma unroll
    for (int h = 0; h < 2; h++) {
      int jb = j0 + h * 64 + tx * 4;
      float o[4];
#pragma unroll
      for (int r = 0; r < 4; r++) {
        int j = jb + r;
        int b = j / NT, t = j - b * NT;
        float mu = fmaxf(__fadd_rn(acc[i][h * 4 + r], bm), 0.f);
        float lv = fmaxf(__fadd_rn(acc[i + 4][h * 4 + r], bl), 0.f);
        float sg = expf(__fmul_rn(0.5f, lv));
        float ev = eps_at((uint32_t)b * 50000u + (uint32_t)f * 100u + (uint32_t)t);
        o[r] = __fadd_rn(mu, __fmul_rn(ev, sg));
      }
      *reinterpret_cast<float4*>(g_psp2 + (size_t)f * J + jb) =
          make_float4(o[0], o[1], o[2], o[3]);
    }
  }
}

// ---------------- kernel 2: dual-exp IIR in place on g_psp2 ------------------
__global__ __launch_bounds__(256) void iir_kernel() {
  __shared__ float s[64 * 101];
  size_t row0 = (size_t)blockIdx.x * 64;
  int tid = threadIdx.x;
  for (int i = tid; i < 6400; i += 256) {
    int r = i / 100, t = i - r * 100;
    s[r * 101 + t] = g_psp2[row0 * 100 + i];
  }
  __syncthreads();
  if (tid < 64) {
    float y1 = 0.f, y2 = 0.f;
    float* row = s + tid * 101;
#pragma unroll
    for (int t = 0; t < NT; t++) {
      float y = __fadd_rn(__fadd_rn(__fmul_rn(A1C, y1), __fmul_rn(A2C, y2)),
                          row[t]);
      row[t] = y;
      y2 = y1; y1 = y;
    }
  }
  __syncthreads();
  for (int i = tid; i < 6400; i += 256) {
    int r = i / 100, t = i - r * 100;
    g_psp2[row0 * 100 + i] = s[r * 101 + t];
  }
}

// ---------------- kernel 3: GEMM2 -> g_cur2[f][J] ----------------------------
// Block tile 128f x 128j, 256 threads, thread 8x8.
__global__ __launch_bounds__(256, 2) void gemm2_kernel(
    const float* __restrict__ W2, const float* __restrict__ b2) {
  __shared__ float Xs[16][128];
  __shared__ float Ws[16][132];
  int j0 = blockIdx.x * 128;
  int f0 = blockIdx.y * 128;
  int tid = threadIdx.x;
  int tx = tid & 15, ty = tid >> 4;

  int kk_s = tid >> 4;                   // X stage row 0..15
  int c_s  = tid & 15;                   // X stage f4 col
  int fi_s = tid & 127;
  int kq   = tid >> 7;
  int wrow = f0 + fi_s;
  bool wok = (wrow < FH);

  float acc[8][8];
#pragma unroll
  for (int i = 0; i < 8; i++)
#pragma unroll
    for (int r = 0; r < 8; r++) acc[i][r] = 0.f;

#pragma unroll 1
  for (int k0 = 0; k0 < 512; k0 += 16) {
    {
      int k = k0 + kk_s;
      float4 v0 = make_float4(0.f, 0.f, 0.f, 0.f), v1 = v0;
      if (k < FH) {
        const float* src = g_psp2 + (size_t)k * J + j0;
        v0 = *reinterpret_cast<const float4*>(src + c_s * 4);
        v1 = *reinterpret_cast<const float4*>(src + 64 + c_s * 4);
      }
      *reinterpret_cast<float4*>(&Xs[kk_s][c_s * 4]) = v0;
      *reinterpret_cast<float4*>(&Xs[kk_s][64 + c_s * 4]) = v1;
    }
#pragma unroll
    for (int q = 0; q < 2; q++) {
      int kb = k0 + kq * 8 + q * 4;
      float4 w = make_float4(0.f, 0.f, 0.f, 0.f);
      if (wok && kb + 3 < FH)
        w = *reinterpret_cast<const float4*>(W2 + (size_t)wrow * FH + kb);
      Ws[kq * 8 + q * 4 + 0][fi_s] = w.x;
      Ws[kq * 8 + q * 4 + 1][fi_s] = w.y;
      Ws[kq * 8 + q * 4 + 2][fi_s] = w.z;
      Ws[kq * 8 + q * 4 + 3][fi_s] = w.w;
    }
    __syncthreads();
#pragma unroll
    for (int kk = 0; kk < 16; kk++) {
      float4 a0 = *reinterpret_cast<const float4*>(&Ws[kk][ty * 4]);
      float4 a1 = *reinterpret_cast<const float4*>(&Ws[kk][ty * 4 + 64]);
      float4 b0 = *reinterpret_cast<const float4*>(&Xs[kk][tx * 4]);
      float4 b1v = *reinterpret_cast<const float4*>(&Xs[kk][tx * 4 + 64]);
      float av[8] = {a0.x, a0.y, a0.z, a0.w, a1.x, a1.y, a1.z, a1.w};
      float bv[8] = {b0.x, b0.y, b0.z, b0.w, b1v.x, b1v.y, b1v.z, b1v.w};
#pragma unroll
      for (int i = 0; i < 8; i++)
#pragma unroll
        for (int r = 0; r < 8; r++)
          acc[i][r] = fmaf(av[i], bv[r], acc[i][r]);
    }
    __syncthreads();
  }

#pragma unroll
  for (int i = 0; i < 8; i++) {
    int f = f0 + ((i < 4) ? (ty * 4 + i) : (64 + ty * 4 + i - 4));
    if (f >= FH) continue;
    float bb = b2[f];
#pragma unroll
    for (int h = 0; h < 2; h++) {
      int jb = j0 + h * 64 + tx * 4;
      float o[4];
#pragma unroll
      for (int r = 0; r < 4; r++)
        o[r] = __fadd_rn(acc[i][h * 4 + r], bb);
      *reinterpret_cast<float4*>(g_cur2 + (size_t)f * J + jb) =
          make_float4(o[0], o[1], o[2], o[3]);
    }
  }
}

// ---------------- kernel 4: LIF + second IIR: g_cur2 -> g_psp3 ---------------
__global__ __launch_bounds__(256) void lifiir_kernel() {
  __shared__ float s[64 * 101];
  size_t row0 = (size_t)blockIdx.x * 64;
  int tid = threadIdx.x;
  for (int i = tid; i < 6400; i += 256) {
    int r = i / 100, t = i - r * 100;
    s[r * 101 + t] = g_cur2[row0 * 100 + i];
  }
  __syncthreads();
  if (tid < 64) {
    float v = 0.f, sp = 0.f, y1 = 0.f, y2 = 0.f;
    float* row = s + tid * 101;
#pragma unroll
    for (int t = 0; t < NT; t++) {
      v = __fadd_rn(__fmul_rn(__fmul_rn(v, EMC), __fadd_rn(1.0f, -sp)), row[t]);
      sp = (v > 1.0f) ? 1.0f : 0.f;
      float y = __fadd_rn(__fadd_rn(__fmul_rn(A1C, y1), __fmul_rn(A2C, y2)), sp);
      row[t] = y;
      y2 = y1; y1 = y;
    }
  }
  __syncthreads();
  for (int i = tid; i < 6400; i += 256) {
    int r = i / 100, t = i - r * 100;
    g_psp3[row0 * 100 + i] = s[r * 101 + t];
  }
}

// ---------------- kernel 5: GEMM3 -> g_cur3[o][J] ----------------------------
// Block: 64 j x 2 output-groups (5 outputs each). 128 threads, grid 400.
__global__ __launch_bounds__(128) void gemm3_kernel(
    const float* __restrict__ W3, const float* __restrict__ b3) {
  __shared__ float Wsm[10 * 512];
  __shared__ float Xs[64][64];
  int j0 = blockIdx.x * 64;
  int tid = threadIdx.x;
  int jj = tid & 63, og = tid >> 6;      // og in {0,1}
  for (int i = tid; i < 10 * 512; i += 128) {
    int o = i >> 9, k = i & 511;
    Wsm[i] = (k < FH) ? W3[o * FH + k] : 0.f;
  }
  __syncthreads();
  float acc[5] = {0.f, 0.f, 0.f, 0.f, 0.f};
#pragma unroll 1
  for (int k0 = 0; k0 < 512; k0 += 64) {
    // stage 64 k x 64 j
#pragma unroll
    for (int s = 0; s < 8; s++) {
      int i = tid + s * 128;            // 0..1023 float4s
      int kk = i >> 4, c4 = i & 15;
      int k = k0 + kk;
      float4 v = make_float4(0.f, 0.f, 0.f, 0.f);
      if (k < FH)
        v = *reinterpret_cast<const float4*>(g_psp3 + (size_t)k * J + j0 + c4 * 4);
      *reinterpret_cast<float4*>(&Xs[kk][c4 * 4]) = v;
    }
    __syncthreads();
#pragma unroll 16
    for (int kk = 0; kk < 64; kk++) {
      float x = Xs[kk][jj];
      int k = k0 + kk;
#pragma unroll
      for (int o = 0; o < 5; o++)
        acc[o] = fmaf(Wsm[(og * 5 + o) * 512 + k], x, acc[o]);
    }
    __syncthreads();
  }
#pragma unroll
  for (int o = 0; o < 5; o++) {
    int oo = og * 5 + o;
    g_cur3[(size_t)oo * J + j0 + jj] = __fadd_rn(acc[o], b3[oo]);
  }
}

// ---------------- kernel 6: LIF layer 3 -> out[b][o][t] ----------------------
__global__ __launch_bounds__(256) void lif3_out_kernel(float* __restrict__ out) {
  __shared__ float s[64 * 101];
  int rid0 = blockIdx.x * 64;     // rid = o*256 + b
  int tid = threadIdx.x;
  for (int i = tid; i < 6400; i += 256) {
    int r = i / 100, t = i - r * 100;
    s[r * 101 + t] = g_cur3[(size_t)rid0 * 100 + i];
  }
  __syncthreads();
  if (tid < 64) {
    int rid = rid0 + tid;
    int o = rid >> 8, b = rid & 255;
    float* po = out + ((size_t)b * 10 + o) * NT;
    const float* row = s + tid * 101;
    float v = 0.f, sp = 0.f;
#pragma unroll
    for (int t = 0; t < NT; t++) {
      v = __fadd_rn(__fmul_rn(__fmul_rn(v, EMC), __fadd_rn(1.0f, -sp)), row[t]);
      sp = (v > 1.0f) ? 1.0f : 0.f;
      po[t] = sp;
    }
  }
}

// ---------------- launcher ---------------------------------------------------
extern "C" void kernel_launch(void* const* d_in, const int* in_sizes, int n_in,
                              void* d_out, int out_size) {
  const float *X = nullptr, *W1 = nullptr, *b1 = nullptr, *W2 = nullptr,
              *b2 = nullptr, *W3 = nullptr, *b3 = nullptr;
  for (int i = 0; i < n_in; i++) {
    switch (in_sizes[i]) {
      case 20070400: X  = (const float*)d_in[i]; break;  // 256*784*100
      case 784000:   W1 = (const float*)d_in[i]; break;  // 1000*784
      case 1000:     b1 = (const float*)d_in[i]; break;
      case 250000:   W2 = (const float*)d_in[i]; break;  // 500*500
      case 500:      b2 = (const float*)d_in[i]; break;
      case 5000:     W3 = (const float*)d_in[i]; break;  // 10*500
      case 10:       b3 = (const float*)d_in[i]; break;
      default: break;
    }
  }
  float* out = (float*)d_out;

  gemm1_kernel<<<dim3(200, 8), 256>>>(X, W1, b1);
  iir_kernel<<<2000, 256>>>();
  gemm2_kernel<<<dim3(200, 4), 256>>>(W2, b2);
  lifiir_kernel<<<2000, 256>>>();
  gemm3_kernel<<<400, 128>>>(W3, b3);
  lif3_out_kernel<<<40, 256>>>(out);
}

// round 9
// speedup vs baseline: 1.8639x; 1.0737x over previous
#include <cuda_runtime.h>
#include <cstdint>
#include <cstddef>

#define NB 256
#define FIN 784
#define FH 500
#define NT 100
#define J 25600                 /* NB*NT flattened column dim */
#define NELEM (FH*J)            /* 12,800,000 */

#define EMC 0.7788007830714049f
#define A1C 1.1466802242428472f
#define A2C (-0.2865047968601901f)

// ---------------- scratch (device globals) -----------------------------------
__device__ float g_psp2[NELEM];  // coding -> (IIR in place) psp2, [f][J]
__device__ float g_cur2[NELEM];  // [f][J]
__device__ float g_psp3[NELEM];  // [f][J]
__device__ float g_cur3[10 * J]; // [o][J]

// ---------------- cp.async helpers -------------------------------------------
__device__ __forceinline__ uint32_t smem_u32(const void* p) {
  return (uint32_t)__cvta_generic_to_shared(p);
}
__device__ __forceinline__ void cp_async4(uint32_t s, const void* g) {
  asm volatile("cp.async.ca.shared.global [%0], [%1], 4;" :: "r"(s), "l"(g));
}
__device__ __forceinline__ void cp_async16z(uint32_t s, const void* g, bool p) {
  int sz = p ? 16 : 0;
  asm volatile("cp.async.cg.shared.global [%0], [%1], 16, %2;"
               :: "r"(s), "l"(g), "r"(sz));
}
#define CP_COMMIT() asm volatile("cp.async.commit_group;")
#define CP_WAIT0()  asm volatile("cp.async.wait_group 0;" ::: "memory")

// ---------------- JAX threefry-2x32, key = (0, 42) ---------------------------
__device__ __forceinline__ uint32_t rotl32(uint32_t v, int d) {
  return (v << d) | (v >> (32 - d));
}

__device__ __forceinline__ void threefry_0_42(uint32_t x0, uint32_t x1,
                                              uint32_t& o0, uint32_t& o1) {
  const uint32_t ks1 = 42u;
  const uint32_t ks2 = 0x1BD11BDAu ^ 42u;
  x1 += ks1;
#define TF_R(d) { x0 += x1; x1 = rotl32(x1, d); x1 ^= x0; }
  TF_R(13) TF_R(15) TF_R(26) TF_R(6)
  x0 += ks1; x1 += ks2 + 1u;
  TF_R(17) TF_R(29) TF_R(16) TF_R(24)
  x0 += ks2; x1 += 2u;
  TF_R(13) TF_R(15) TF_R(26) TF_R(6)
  x0 += 0u; x1 += ks1 + 3u;
  TF_R(17) TF_R(29) TF_R(16) TF_R(24)
  x0 += ks1; x1 += ks2 + 4u;
  TF_R(13) TF_R(15) TF_R(26) TF_R(6)
  x0 += ks2; x1 += 5u;
#undef TF_R
  o0 = x0; o1 = x1;
}

__device__ __forceinline__ float erfinv_xla(float x) {
  float nx2 = __fmul_rn(x, x);
  float w = -log1pf(-nx2);
  float p;
  if (w < 5.0f) {
    w = __fadd_rn(w, -2.5f);
    p = 2.81022636e-08f;
    p = __fadd_rn(3.43273939e-07f, __fmul_rn(p, w));
    p = __fadd_rn(-3.5233877e-06f, __fmul_rn(p, w));
    p = __fadd_rn(-4.39150654e-06f, __fmul_rn(p, w));
    p = __fadd_rn(0.00021858087f, __fmul_rn(p, w));
    p = __fadd_rn(-0.00125372503f, __fmul_rn(p, w));
    p = __fadd_rn(-0.00417768164f, __fmul_rn(p, w));
    p = __fadd_rn(0.246640727f, __fmul_rn(p, w));
    p = __fadd_rn(1.50140941f, __fmul_rn(p, w));
  } else {
    w = __fadd_rn(sqrtf(w), -3.0f);
    p = -0.000200214257f;
    p = __fadd_rn(0.000100950558f, __fmul_rn(p, w));
    p = __fadd_rn(0.00134934322f, __fmul_rn(p, w));
    p = __fadd_rn(-0.00367342844f, __fmul_rn(p, w));
    p = __fadd_rn(0.00573950773f, __fmul_rn(p, w));
    p = __fadd_rn(-0.0076224613f, __fmul_rn(p, w));
    p = __fadd_rn(0.00943887047f, __fmul_rn(p, w));
    p = __fadd_rn(1.00167406f, __fmul_rn(p, w));
    p = __fadd_rn(2.83297682f, __fmul_rn(p, w));
  }
  return __fmul_rn(p, x);
}

__device__ __forceinline__ float eps_at(uint32_t ctr) {
  uint32_t r0, r1;
  threefry_0_42(0u, ctr, r0, r1);
  uint32_t bits = r0 ^ r1;
  const float lo = -0.99999994039535522461f;
  float f = __fadd_rn(__uint_as_float((bits >> 9) | 0x3f800000u), -1.0f);
  float u = __fadd_rn(__fmul_rn(f, 2.0f), lo);
  u = fmaxf(u, lo);
  return __fmul_rn(1.4142135623730951f, erfinv_xla(u));
}

// ---------------- kernel 1: GEMM1 + relu + coding(+eps) -> g_psp2[f][J] ------
// Block tile: 128 M-rows (64 mu + 64 lv) x 128 j, 256 threads, 8x8 thread tile.
// Double-buffered: X via cp.async, W via reg-prefetch + post-compute STS.
__global__ __launch_bounds__(256, 2) void gemm1_kernel(
    const float* __restrict__ X, const float* __restrict__ W1,
    const float* __restrict__ b1) {
  __shared__ float Xs[2][16][128];
  __shared__ float Ws[2][16][132];
  int j0 = blockIdx.x * 128;
  int f0 = blockIdx.y * 64;
  int tid = threadIdx.x;
  int tx = tid & 15, ty = tid >> 4;

  int jj_s = tid & 127;
  int kh   = tid >> 7;                   // 0/1 -> which 8 k's
  int ja = j0 + jj_s;
  const float* pxa = X + (size_t)(ja / NT) * (FIN * NT) + (ja % NT);
  int fi_s = tid & 127;
  int kq   = tid >> 7;
  int flog = f0 + (fi_s & 63);
  int wrow = (fi_s < 64) ? flog : (flog + FH);
  bool wok = (flog < FH);
  const float* wptr = W1 + (size_t)(wok ? wrow : 0) * FIN;

  float acc[8][8];
#pragma unroll
  for (int i = 0; i < 8; i++)
#pragma unroll
    for (int r = 0; r < 8; r++) acc[i][r] = 0.f;

  float4 wr[2];
  const int NCH = FIN / 16;              // 49 exact chunks

  // prologue: chunk 0 into buffer 0
#pragma unroll
  for (int m = 0; m < 8; m++)
    cp_async4(smem_u32(&Xs[0][kh * 8 + m][jj_s]),
              pxa + (size_t)(kh * 8 + m) * NT);
  CP_COMMIT();
#pragma unroll
  for (int q = 0; q < 2; q++) {
    wr[q] = make_float4(0.f, 0.f, 0.f, 0.f);
    if (wok) wr[q] = *reinterpret_cast<const float4*>(wptr + kq * 8 + q * 4);
  }
#pragma unroll
  for (int q = 0; q < 2; q++) {
    Ws[0][kq * 8 + q * 4 + 0][fi_s] = wr[q].x;
    Ws[0][kq * 8 + q * 4 + 1][fi_s] = wr[q].y;
    Ws[0][kq * 8 + q * 4 + 2][fi_s] = wr[q].z;
    Ws[0][kq * 8 + q * 4 + 3][fi_s] = wr[q].w;
  }
  CP_WAIT0();
  __syncthreads();

#pragma unroll 1
  for (int c = 0; c < NCH; c++) {
    int cur = c & 1;
    bool more = (c + 1 < NCH);
    if (more) {
      int k0 = (c + 1) * 16;
#pragma unroll
      for (int m = 0; m < 8; m++)
        cp_async4(smem_u32(&Xs[cur ^ 1][kh * 8 + m][jj_s]),
                  pxa + (size_t)(k0 + kh * 8 + m) * NT);
      CP_COMMIT();
#pragma unroll
      for (int q = 0; q < 2; q++) {
        wr[q] = make_float4(0.f, 0.f, 0.f, 0.f);
        if (wok)
          wr[q] = *reinterpret_cast<const float4*>(wptr + k0 + kq * 8 + q * 4);
      }
    }
#pragma unroll
    for (int kk = 0; kk < 16; kk++) {
      float4 a0 = *reinterpret_cast<const float4*>(&Ws[cur][kk][ty * 4]);
      float4 a1 = *reinterpret_cast<const float4*>(&Ws[cur][kk][ty * 4 + 64]);
      float4 b0 = *reinterpret_cast<const float4*>(&Xs[cur][kk][tx * 4]);
      float4 b1v = *reinterpret_cast<const float4*>(&Xs[cur][kk][tx * 4 + 64]);
      float av[8] = {a0.x, a0.y, a0.z, a0.w, a1.x, a1.y, a1.z, a1.w};
      float bv[8] = {b0.x, b0.y, b0.z, b0.w, b1v.x, b1v.y, b1v.z, b1v.w};
#pragma unroll
      for (int i = 0; i < 8; i++)
#pragma unroll
        for (int r = 0; r < 8; r++)
          acc[i][r] = fmaf(av[i], bv[r], acc[i][r]);
    }
    if (more) {
#pragma unroll
      for (int q = 0; q < 2; q++) {
        Ws[cur ^ 1][kq * 8 + q * 4 + 0][fi_s] = wr[q].x;
        Ws[cur ^ 1][kq * 8 + q * 4 + 1][fi_s] = wr[q].y;
        Ws[cur ^ 1][kq * 8 + q * 4 + 2][fi_s] = wr[q].z;
        Ws[cur ^ 1][kq * 8 + q * 4 + 3][fi_s] = wr[q].w;
      }
      CP_WAIT0();
      __syncthreads();
    }
  }

  // epilogue: acc[i] (i<4) = mu row f0+ty*4+i; acc[i+4] = paired lnvar row.
#pragma unroll
  for (int i = 0; i < 4; i++) {
    int f = f0 + ty * 4 + i;
    if (f >= FH) continue;
    float bm = b1[f], bl = b1[f + FH];
#pragma unroll
    for (int h = 0; h < 2; h++) {
      int jb = j0 + h * 64 + tx * 4;
      float o[4];
#pragma unroll
      for (int r = 0; r < 4; r++) {
        int j = jb + r;
        int b = j / NT, t = j - b * NT;
        float mu = fmaxf(__fadd_rn(acc[i][h * 4 + r], bm), 0.f);
        float lv = fmaxf(__fadd_rn(acc[i + 4][h * 4 + r], bl), 0.f);
        float sg = expf(__fmul_rn(0.5f, lv));
        float ev = eps_at((uint32_t)b * 50000u + (uint32_t)f * 100u + (uint32_t)t);
        o[r] = __fadd_rn(mu, __fmul_rn(ev, sg));
      }
      *reinterpret_cast<float4*>(g_psp2 + (size_t)f * J + jb) =
          make_float4(o[0], o[1], o[2], o[3]);
    }
  }
}

// ---------------- kernel 2: dual-exp IIR in place on g_psp2 ------------------
__global__ __launch_bounds__(256) void iir_kernel() {
  __shared__ float s[64 * 101];
  size_t row0 = (size_t)blockIdx.x * 64;
  int tid = threadIdx.x;
  for (int i = tid; i < 6400; i += 256) {
    int r = i / 100, t = i - r * 100;
    s[r * 101 + t] = g_psp2[row0 * 100 + i];
  }
  __syncthreads();
  if (tid < 64) {
    float y1 = 0.f, y2 = 0.f;
    float* row = s + tid * 101;
#pragma unroll
    for (int t = 0; t < NT; t++) {
      float y = __fadd_rn(__fadd_rn(__fmul_rn(A1C, y1), __fmul_rn(A2C, y2)),
                          row[t]);
      row[t] = y;
      y2 = y1; y1 = y;
    }
  }
  __syncthreads();
  for (int i = tid; i < 6400; i += 256) {
    int r = i / 100, t = i - r * 100;
    g_psp2[row0 * 100 + i] = s[r * 101 + t];
  }
}

// ---------------- kernel 3: GEMM2 -> g_cur2[f][J] ----------------------------
// Block tile 128f x 128j, 256 threads, 8x8; double-buffered like gemm1.
__global__ __launch_bounds__(256, 2) void gemm2_kernel(
    const float* __restrict__ W2, const float* __restrict__ b2) {
  __shared__ float Xs[2][16][128];
  __shared__ float Ws[2][16][132];
  int j0 = blockIdx.x * 128;
  int f0 = blockIdx.y * 128;
  int tid = threadIdx.x;
  int tx = tid & 15, ty = tid >> 4;

  int kk_s = tid >> 4;                   // X stage row 0..15
  int c_s  = tid & 15;                   // X stage f4 col
  const float* xsrc = g_psp2 + j0 + c_s * 4;
  int fi_s = tid & 127;
  int kq   = tid >> 7;
  int wrow = f0 + fi_s;
  bool wok = (wrow < FH);
  const float* wptr = W2 + (size_t)(wok ? wrow : 0) * FH;

  float acc[8][8];
#pragma unroll
  for (int i = 0; i < 8; i++)
#pragma unroll
    for (int r = 0; r < 8; r++) acc[i][r] = 0.f;

  float4 wr[2];
  const int NCH = 32;                    // 512 k padded

  // prologue: chunk 0
  {
    bool xp = (kk_s < FH);
    cp_async16z(smem_u32(&Xs[0][kk_s][c_s * 4]),
                xsrc + (size_t)kk_s * J, xp);
    cp_async16z(smem_u32(&Xs[0][kk_s][64 + c_s * 4]),
                xsrc + (size_t)kk_s * J + 64, xp);
    CP_COMMIT();
#pragma unroll
    for (int q = 0; q < 2; q++) {
      int kb = kq * 8 + q * 4;
      wr[q] = make_float4(0.f, 0.f, 0.f, 0.f);
      if (wok && kb < FH)
        wr[q] = *reinterpret_cast<const float4*>(wptr + kb);
    }
#pragma unroll
    for (int q = 0; q < 2; q++) {
      Ws[0][kq * 8 + q * 4 + 0][fi_s] = wr[q].x;
      Ws[0][kq * 8 + q * 4 + 1][fi_s] = wr[q].y;
      Ws[0][kq * 8 + q * 4 + 2][fi_s] = wr[q].z;
      Ws[0][kq * 8 + q * 4 + 3][fi_s] = wr[q].w;
    }
    CP_WAIT0();
    __syncthreads();
  }

#pragma unroll 1
  for (int c = 0; c < NCH; c++) {
    int cur = c & 1;
    bool more = (c + 1 < NCH);
    if (more) {
      int k0 = (c + 1) * 16;
      bool xp = (k0 + kk_s < FH);
      cp_async16z(smem_u32(&Xs[cur ^ 1][kk_s][c_s * 4]),
                  xsrc + (size_t)(k0 + kk_s) * J, xp);
      cp_async16z(smem_u32(&Xs[cur ^ 1][kk_s][64 + c_s * 4]),
                  xsrc + (size_t)(k0 + kk_s) * J + 64, xp);
      CP_COMMIT();
#pragma unroll
      for (int q = 0; q < 2; q++) {
        int kb = k0 + kq * 8 + q * 4;
        wr[q] = make_float4(0.f, 0.f, 0.f, 0.f);
        if (wok && kb < FH)
          wr[q] = *reinterpret_cast<const float4*>(wptr + kb);
      }
    }
#pragma unroll
    for (int kk = 0; kk < 16; kk++) {
      float4 a0 = *reinterpret_cast<const float4*>(&Ws[cur][kk][ty * 4]);
      float4 a1 = *reinterpret_cast<const float4*>(&Ws[cur][kk][ty * 4 + 64]);
      float4 b0 = *reinterpret_cast<const float4*>(&Xs[cur][kk][tx * 4]);
      float4 b1v = *reinterpret_cast<const float4*>(&Xs[cur][kk][tx * 4 + 64]);
      float av[8] = {a0.x, a0.y, a0.z, a0.w, a1.x, a1.y, a1.z, a1.w};
      float bv[8] = {b0.x, b0.y, b0.z, b0.w, b1v.x, b1v.y, b1v.z, b1v.w};
#pragma unroll
      for (int i = 0; i < 8; i++)
#pragma unroll
        for (int r = 0; r < 8; r++)
          acc[i][r] = fmaf(av[i], bv[r], acc[i][r]);
    }
    if (more) {
#pragma unroll
      for (int q = 0; q < 2; q++) {
        Ws[cur ^ 1][kq * 8 + q * 4 + 0][fi_s] = wr[q].x;
        Ws[cur ^ 1][kq * 8 + q * 4 + 1][fi_s] = wr[q].y;
        Ws[cur ^ 1][kq * 8 + q * 4 + 2][fi_s] = wr[q].z;
        Ws[cur ^ 1][kq * 8 + q * 4 + 3][fi_s] = wr[q].w;
      }
      CP_WAIT0();
      __syncthreads();
    }
  }

#pragma unroll
  for (int i = 0; i < 8; i++) {
    int f = f0 + ((i < 4) ? (ty * 4 + i) : (64 + ty * 4 + i - 4));
    if (f >= FH) continue;
    float bb = b2[f];
#pragma unroll
    for (int h = 0; h < 2; h++) {
      int jb = j0 + h * 64 + tx * 4;
      float o[4];
#pragma unroll
      for (int r = 0; r < 4; r++)
        o[r] = __fadd_rn(acc[i][h * 4 + r], bb);
      *reinterpret_cast<float4*>(g_cur2 + (size_t)f * J + jb) =
          make_float4(o[0], o[1], o[2], o[3]);
    }
  }
}

// ---------------- kernel 4: LIF + second IIR: g_cur2 -> g_psp3 ---------------
__global__ __launch_bounds__(256) void lifiir_kernel() {
  __shared__ float s[64 * 101];
  size_t row0 = (size_t)blockIdx.x * 64;
  int tid = threadIdx.x;
  for (int i = tid; i < 6400; i += 256) {
    int r = i / 100, t = i - r * 100;
    s[r * 101 + t] = g_cur2[row0 * 100 + i];
  }
  __syncthreads();
  if (tid < 64) {
    float v = 0.f, sp = 0.f, y1 = 0.f, y2 = 0.f;
    float* row = s + tid * 101;
#pragma unroll
    for (int t = 0; t < NT; t++) {
      v = __fadd_rn(__fmul_rn(__fmul_rn(v, EMC), __fadd_rn(1.0f, -sp)), row[t]);
      sp = (v > 1.0f) ? 1.0f : 0.f;
      float y = __fadd_rn(__fadd_rn(__fmul_rn(A1C, y1), __fmul_rn(A2C, y2)), sp);
      row[t] = y;
      y2 = y1; y1 = y;
    }
  }
  __syncthreads();
  for (int i = tid; i < 6400; i += 256) {
    int r = i / 100, t = i - r * 100;
    g_psp3[row0 * 100 + i] = s[r * 101 + t];
  }
}

// ---------------- kernel 5: GEMM3 -> g_cur3[o][J] ----------------------------
__global__ __launch_bounds__(128) void gemm3_kernel(
    const float* __restrict__ W3, const float* __restrict__ b3) {
  __shared__ float Wsm[10 * 512];
  __shared__ float Xs[64][64];
  int j0 = blockIdx.x * 64;
  int tid = threadIdx.x;
  int jj = tid & 63, og = tid >> 6;      // og in {0,1}
  for (int i = tid; i < 10 * 512; i += 128) {
    int o = i >> 9, k = i & 511;
    Wsm[i] = (k < FH) ? W3[o * FH + k] : 0.f;
  }
  __syncthreads();
  float acc[5] = {0.f, 0.f, 0.f, 0.f, 0.f};
#pragma unroll 1
  for (int k0 = 0; k0 < 512; k0 += 64) {
#pragma unroll
    for (int s = 0; s < 8; s++) {
      int i = tid + s * 128;
      int kk = i >> 4, c4 = i & 15;
      int k = k0 + kk;
      float4 v = make_float4(0.f, 0.f, 0.f, 0.f);
      if (k < FH)
        v = *reinterpret_cast<const float4*>(g_psp3 + (size_t)k * J + j0 + c4 * 4);
      *reinterpret_cast<float4*>(&Xs[kk][c4 * 4]) = v;
    }
    __syncthreads();
#pragma unroll 16
    for (int kk = 0; kk < 64; kk++) {
      float x = Xs[kk][jj];
      int k = k0 + kk;
#pragma unroll
      for (int o = 0; o < 5; o++)
        acc[o] = fmaf(Wsm[(og * 5 + o) * 512 + k], x, acc[o]);
    }
    __syncthreads();
  }
#pragma unroll
  for (int o = 0; o < 5; o++) {
    int oo = og * 5 + o;
    g_cur3[(size_t)oo * J + j0 + jj] = __fadd_rn(acc[o], b3[oo]);
  }
}

// ---------------- kernel 6: LIF layer 3 -> out[b][o][t] ----------------------
__global__ __launch_bounds__(256) void lif3_out_kernel(float* __restrict__ out) {
  __shared__ float s[64 * 101];
  int rid0 = blockIdx.x * 64;     // rid = o*256 + b
  int tid = threadIdx.x;
  for (int i = tid; i < 6400; i += 256) {
    int r = i / 100, t = i - r * 100;
    s[r * 101 + t] = g_cur3[(size_t)rid0 * 100 + i];
  }
  __syncthreads();
  if (tid < 64) {
    int rid = rid0 + tid;
    int o = rid >> 8, b = rid & 255;
    float* po = out + ((size_t)b * 10 + o) * NT;
    const float* row = s + tid * 101;
    float v = 0.f, sp = 0.f;
#pragma unroll
    for (int t = 0; t < NT; t++) {
      v = __fadd_rn(__fmul_rn(__fmul_rn(v, EMC), __fadd_rn(1.0f, -sp)), row[t]);
      sp = (v > 1.0f) ? 1.0f : 0.f;
      po[t] = sp;
    }
  }
}

// ---------------- launcher ---------------------------------------------------
extern "C" void kernel_launch(void* const* d_in, const int* in_sizes, int n_in,
                              void* d_out, int out_size) {
  const float *X = nullptr, *W1 = nullptr, *b1 = nullptr, *W2 = nullptr,
              *b2 = nullptr, *W3 = nullptr, *b3 = nullptr;
  for (int i = 0; i < n_in; i++) {
    switch (in_sizes[i]) {
      case 20070400: X  = (const float*)d_in[i]; break;  // 256*784*100
      case 784000:   W1 = (const float*)d_in[i]; break;  // 1000*784
      case 1000:     b1 = (const float*)d_in[i]; break;
      case 250000:   W2 = (const float*)d_in[i]; break;  // 500*500
      case 500:      b2 = (const float*)d_in[i]; break;
      case 5000:     W3 = (const float*)d_in[i]; break;  // 10*500
      case 10:       b3 = (const float*)d_in[i]; break;
      default: break;
    }
  }
  float* out = (float*)d_out;

  gemm1_kernel<<<dim3(200, 8), 256>>>(X, W1, b1);
  iir_kernel<<<2000, 256>>>();
  gemm2_kernel<<<dim3(200, 4), 256>>>(W2, b2);
  lifiir_kernel<<<2000, 256>>>();
  gemm3_kernel<<<400, 128>>>(W3, b3);
  lif3_out_kernel<<<40, 256>>>(out);
}

// round 10
// speedup vs baseline: 2.0801x; 1.1160x over previous
#include <cuda_runtime.h>
#include <cstdint>
#include <cstddef>

#define NB 256
#define FIN 784
#define FH 500
#define NT 100
#define J 25600                 /* NB*NT flattened column dim */
#define NELEM (FH*J)            /* 12,800,000 */

#define EMC 0.7788007830714049f
#define A1C 1.1466802242428472f
#define A2C (-0.2865047968601901f)

// ---------------- scratch (device globals) -----------------------------------
__device__ float g_psp2[NELEM];  // coding -> (IIR in place) psp2, [f][J]
__device__ float g_cur2[NELEM];  // [f][J]
__device__ float g_psp3[NELEM];  // [f][J]
__device__ float g_cur3[10 * J]; // [o][J]

// ---------------- cp.async helpers -------------------------------------------
__device__ __forceinline__ uint32_t smem_u32(const void* p) {
  return (uint32_t)__cvta_generic_to_shared(p);
}
__device__ __forceinline__ void cp_async4(uint32_t s, const void* g) {
  asm volatile("cp.async.ca.shared.global [%0], [%1], 4;" :: "r"(s), "l"(g));
}
__device__ __forceinline__ void cp_async16z(uint32_t s, const void* g, bool p) {
  int sz = p ? 16 : 0;
  asm volatile("cp.async.cg.shared.global [%0], [%1], 16, %2;"
               :: "r"(s), "l"(g), "r"(sz));
}
#define CP_COMMIT() asm volatile("cp.async.commit_group;")
#define CP_WAIT0()  asm volatile("cp.async.wait_group 0;" ::: "memory")

// ---------------- packed fp32x2 FMA (Blackwell FFMA2) ------------------------
__device__ __forceinline__ unsigned long long pack2(float a) {
  unsigned long long d;
  asm("mov.b64 %0, {%1, %1};" : "=l"(d) : "f"(a));
  return d;
}
__device__ __forceinline__ void fma2(unsigned long long& d,
                                     unsigned long long a,
                                     unsigned long long b) {
  asm("fma.rn.f32x2 %0, %1, %2, %3;" : "=l"(d) : "l"(a), "l"(b), "l"(d));
}
__device__ __forceinline__ float2 unpack2(unsigned long long v) {
  float lo, hi;
  asm("mov.b64 {%0, %1}, %2;" : "=f"(lo), "=f"(hi) : "l"(v));
  return make_float2(lo, hi);
}

// ---------------- JAX threefry-2x32, key = (0, 42) ---------------------------
__device__ __forceinline__ uint32_t rotl32(uint32_t v, int d) {
  return (v << d) | (v >> (32 - d));
}

__device__ __forceinline__ void threefry_0_42(uint32_t x0, uint32_t x1,
                                              uint32_t& o0, uint32_t& o1) {
  const uint32_t ks1 = 42u;
  const uint32_t ks2 = 0x1BD11BDAu ^ 42u;
  x1 += ks1;
#define TF_R(d) { x0 += x1; x1 = rotl32(x1, d); x1 ^= x0; }
  TF_R(13) TF_R(15) TF_R(26) TF_R(6)
  x0 += ks1; x1 += ks2 + 1u;
  TF_R(17) TF_R(29) TF_R(16) TF_R(24)
  x0 += ks2; x1 += 2u;
  TF_R(13) TF_R(15) TF_R(26) TF_R(6)
  x0 += 0u; x1 += ks1 + 3u;
  TF_R(17) TF_R(29) TF_R(16) TF_R(24)
  x0 += ks1; x1 += ks2 + 4u;
  TF_R(13) TF_R(15) TF_R(26) TF_R(6)
  x0 += ks2; x1 += 5u;
#undef TF_R
  o0 = x0; o1 = x1;
}

__device__ __forceinline__ float erfinv_xla(float x) {
  float nx2 = __fmul_rn(x, x);
  float w = -log1pf(-nx2);
  float p;
  if (w < 5.0f) {
    w = __fadd_rn(w, -2.5f);
    p = 2.81022636e-08f;
    p = __fadd_rn(3.43273939e-07f, __fmul_rn(p, w));
    p = __fadd_rn(-3.5233877e-06f, __fmul_rn(p, w));
    p = __fadd_rn(-4.39150654e-06f, __fmul_rn(p, w));
    p = __fadd_rn(0.00021858087f, __fmul_rn(p, w));
    p = __fadd_rn(-0.00125372503f, __fmul_rn(p, w));
    p = __fadd_rn(-0.00417768164f, __fmul_rn(p, w));
    p = __fadd_rn(0.246640727f, __fmul_rn(p, w));
    p = __fadd_rn(1.50140941f, __fmul_rn(p, w));
  } else {
    w = __fadd_rn(sqrtf(w), -3.0f);
    p = -0.000200214257f;
    p = __fadd_rn(0.000100950558f, __fmul_rn(p, w));
    p = __fadd_rn(0.00134934322f, __fmul_rn(p, w));
    p = __fadd_rn(-0.00367342844f, __fmul_rn(p, w));
    p = __fadd_rn(0.00573950773f, __fmul_rn(p, w));
    p = __fadd_rn(-0.0076224613f, __fmul_rn(p, w));
    p = __fadd_rn(0.00943887047f, __fmul_rn(p, w));
    p = __fadd_rn(1.00167406f, __fmul_rn(p, w));
    p = __fadd_rn(2.83297682f, __fmul_rn(p, w));
  }
  return __fmul_rn(p, x);
}

__device__ __forceinline__ float eps_at(uint32_t ctr) {
  uint32_t r0, r1;
  threefry_0_42(0u, ctr, r0, r1);
  uint32_t bits = r0 ^ r1;
  const float lo = -0.99999994039535522461f;
  float f = __fadd_rn(__uint_as_float((bits >> 9) | 0x3f800000u), -1.0f);
  float u = __fadd_rn(__fmul_rn(f, 2.0f), lo);
  u = fmaxf(u, lo);
  return __fmul_rn(1.4142135623730951f, erfinv_xla(u));
}

// ---------------- kernel 1: GEMM1 + relu + coding(+eps) -> g_psp2[f][J] ------
// Block tile: 128 M-rows (64 mu + 64 lv) x 128 j, 256 threads, 8x8 thread tile.
// j-accumulators packed in pairs; inner loop uses fma.rn.f32x2 (FFMA2).
__global__ __launch_bounds__(256, 2) void gemm1_kernel(
    const float* __restrict__ X, const float* __restrict__ W1,
    const float* __restrict__ b1) {
  __shared__ float Xs[2][16][128];
  __shared__ float Ws[2][16][132];
  int j0 = blockIdx.x * 128;
  int f0 = blockIdx.y * 64;
  int tid = threadIdx.x;
  int tx = tid & 15, ty = tid >> 4;

  int jj_s = tid & 127;
  int kh   = tid >> 7;                   // 0/1 -> which 8 k's
  int ja = j0 + jj_s;
  const float* pxa = X + (size_t)(ja / NT) * (FIN * NT) + (ja % NT);
  int fi_s = tid & 127;
  int kq   = tid >> 7;
  int flog = f0 + (fi_s & 63);
  int wrow = (fi_s < 64) ? flog : (flog + FH);
  bool wok = (flog < FH);
  const float* wptr = W1 + (size_t)(wok ? wrow : 0) * FIN;

  unsigned long long acc2[8][4];
#pragma unroll
  for (int i = 0; i < 8; i++)
#pragma unroll
    for (int p = 0; p < 4; p++) acc2[i][p] = 0ull;

  float4 wr[2];
  const int NCH = FIN / 16;              // 49 exact chunks

  // prologue: chunk 0 into buffer 0
#pragma unroll
  for (int m = 0; m < 8; m++)
    cp_async4(smem_u32(&Xs[0][kh * 8 + m][jj_s]),
              pxa + (size_t)(kh * 8 + m) * NT);
  CP_COMMIT();
#pragma unroll
  for (int q = 0; q < 2; q++) {
    wr[q] = make_float4(0.f, 0.f, 0.f, 0.f);
    if (wok) wr[q] = *reinterpret_cast<const float4*>(wptr + kq * 8 + q * 4);
  }
#pragma unroll
  for (int q = 0; q < 2; q++) {
    Ws[0][kq * 8 + q * 4 + 0][fi_s] = wr[q].x;
    Ws[0][kq * 8 + q * 4 + 1][fi_s] = wr[q].y;
    Ws[0][kq * 8 + q * 4 + 2][fi_s] = wr[q].z;
    Ws[0][kq * 8 + q * 4 + 3][fi_s] = wr[q].w;
  }
  CP_WAIT0();
  __syncthreads();

#pragma unroll 1
  for (int c = 0; c < NCH; c++) {
    int cur = c & 1;
    bool more = (c + 1 < NCH);
    if (more) {
      int k0 = (c + 1) * 16;
#pragma unroll
      for (int m = 0; m < 8; m++)
        cp_async4(smem_u32(&Xs[cur ^ 1][kh * 8 + m][jj_s]),
                  pxa + (size_t)(k0 + kh * 8 + m) * NT);
      CP_COMMIT();
#pragma unroll
      for (int q = 0; q < 2; q++) {
        wr[q] = make_float4(0.f, 0.f, 0.f, 0.f);
        if (wok)
          wr[q] = *reinterpret_cast<const float4*>(wptr + k0 + kq * 8 + q * 4);
      }
    }
#pragma unroll
    for (int kk = 0; kk < 16; kk++) {
      float4 a0 = *reinterpret_cast<const float4*>(&Ws[cur][kk][ty * 4]);
      float4 a1 = *reinterpret_cast<const float4*>(&Ws[cur][kk][ty * 4 + 64]);
      ulonglong2 bq0 = *reinterpret_cast<const ulonglong2*>(&Xs[cur][kk][tx * 4]);
      ulonglong2 bq1 = *reinterpret_cast<const ulonglong2*>(&Xs[cur][kk][tx * 4 + 64]);
      unsigned long long bp[4] = {bq0.x, bq0.y, bq1.x, bq1.y};
      float av[8] = {a0.x, a0.y, a0.z, a0.w, a1.x, a1.y, a1.z, a1.w};
#pragma unroll
      for (int i = 0; i < 8; i++) {
        unsigned long long ap = pack2(av[i]);
#pragma unroll
        for (int p = 0; p < 4; p++) fma2(acc2[i][p], ap, bp[p]);
      }
    }
    if (more) {
#pragma unroll
      for (int q = 0; q < 2; q++) {
        Ws[cur ^ 1][kq * 8 + q * 4 + 0][fi_s] = wr[q].x;
        Ws[cur ^ 1][kq * 8 + q * 4 + 1][fi_s] = wr[q].y;
        Ws[cur ^ 1][kq * 8 + q * 4 + 2][fi_s] = wr[q].z;
        Ws[cur ^ 1][kq * 8 + q * 4 + 3][fi_s] = wr[q].w;
      }
      CP_WAIT0();
      __syncthreads();
    }
  }

  // epilogue: acc2[i] (i<4) = mu row f0+ty*4+i; acc2[i+4] = paired lnvar row.
  // pair p = h*2 + (r>>1), halves are (j, j+1).
#pragma unroll
  for (int i = 0; i < 4; i++) {
    int f = f0 + ty * 4 + i;
    if (f >= FH) continue;
    float bm = b1[f], bl = b1[f + FH];
#pragma unroll
    for (int h = 0; h < 2; h++) {
      int jb = j0 + h * 64 + tx * 4;
      float2 m0 = unpack2(acc2[i][h * 2]);
      float2 m1 = unpack2(acc2[i][h * 2 + 1]);
      float2 l0 = unpack2(acc2[i + 4][h * 2]);
      float2 l1 = unpack2(acc2[i + 4][h * 2 + 1]);
      float am[4] = {m0.x, m0.y, m1.x, m1.y};
      float al[4] = {l0.x, l0.y, l1.x, l1.y};
      float o[4];
#pragma unroll
      for (int r = 0; r < 4; r++) {
        int j = jb + r;
        int b = j / NT, t = j - b * NT;
        float mu = fmaxf(__fadd_rn(am[r], bm), 0.f);
        float lv = fmaxf(__fadd_rn(al[r], bl), 0.f);
        float sg = expf(__fmul_rn(0.5f, lv));
        float ev = eps_at((uint32_t)b * 50000u + (uint32_t)f * 100u + (uint32_t)t);
        o[r] = __fadd_rn(mu, __fmul_rn(ev, sg));
      }
      *reinterpret_cast<float4*>(g_psp2 + (size_t)f * J + jb) =
          make_float4(o[0], o[1], o[2], o[3]);
    }
  }
}

// ---------------- kernel 2: dual-exp IIR in place on g_psp2 ------------------
__global__ __launch_bounds__(256) void iir_kernel() {
  __shared__ float s[64 * 101];
  size_t row0 = (size_t)blockIdx.x * 64;
  int tid = threadIdx.x;
  for (int i = tid; i < 6400; i += 256) {
    int r = i / 100, t = i - r * 100;
    s[r * 101 + t] = g_psp2[row0 * 100 + i];
  }
  __syncthreads();
  if (tid < 64) {
    float y1 = 0.f, y2 = 0.f;
    float* row = s + tid * 101;
#pragma unroll
    for (int t = 0; t < NT; t++) {
      float y = __fadd_rn(__fadd_rn(__fmul_rn(A1C, y1), __fmul_rn(A2C, y2)),
                          row[t]);
      row[t] = y;
      y2 = y1; y1 = y;
    }
  }
  __syncthreads();
  for (int i = tid; i < 6400; i += 256) {
    int r = i / 100, t = i - r * 100;
    g_psp2[row0 * 100 + i] = s[r * 101 + t];
  }
}

// ---------------- kernel 3: GEMM2 -> g_cur2[f][J] ----------------------------
// Block tile 128f x 128j, 256 threads, 8x8; FFMA2 inner loop.
__global__ __launch_bounds__(256, 2) void gemm2_kernel(
    const float* __restrict__ W2, const float* __restrict__ b2) {
  __shared__ float Xs[2][16][128];
  __shared__ float Ws[2][16][132];
  int j0 = blockIdx.x * 128;
  int f0 = blockIdx.y * 128;
  int tid = threadIdx.x;
  int tx = tid & 15, ty = tid >> 4;

  int kk_s = tid >> 4;                   // X stage row 0..15
  int c_s  = tid & 15;                   // X stage f4 col
  const float* xsrc = g_psp2 + j0 + c_s * 4;
  int fi_s = tid & 127;
  int kq   = tid >> 7;
  int wrow = f0 + fi_s;
  bool wok = (wrow < FH);
  const float* wptr = W2 + (size_t)(wok ? wrow : 0) * FH;

  unsigned long long acc2[8][4];
#pragma unroll
  for (int i = 0; i < 8; i++)
#pragma unroll
    for (int p = 0; p < 4; p++) acc2[i][p] = 0ull;

  float4 wr[2];
  const int NCH = 32;                    // 512 k padded

  // prologue: chunk 0
  {
    bool xp = (kk_s < FH);
    cp_async16z(smem_u32(&Xs[0][kk_s][c_s * 4]),
                xsrc + (size_t)kk_s * J, xp);
    cp_async16z(smem_u32(&Xs[0][kk_s][64 + c_s * 4]),
                xsrc + (size_t)kk_s * J + 64, xp);
    CP_COMMIT();
#pragma unroll
    for (int q = 0; q < 2; q++) {
      int kb = kq * 8 + q * 4;
      wr[q] = make_float4(0.f, 0.f, 0.f, 0.f);
      if (wok && kb < FH)
        wr[q] = *reinterpret_cast<const float4*>(wptr + kb);
    }
#pragma unroll
    for (int q = 0; q < 2; q++) {
      Ws[0][kq * 8 + q * 4 + 0][fi_s] = wr[q].x;
      Ws[0][kq * 8 + q * 4 + 1][fi_s] = wr[q].y;
      Ws[0][kq * 8 + q * 4 + 2][fi_s] = wr[q].z;
      Ws[0][kq * 8 + q * 4 + 3][fi_s] = wr[q].w;
    }
    CP_WAIT0();
    __syncthreads();
  }

#pragma unroll 1
  for (int c = 0; c < NCH; c++) {
    int cur = c & 1;
    bool more = (c + 1 < NCH);
    if (more) {
      int k0 = (c + 1) * 16;
      bool xp = (k0 + kk_s < FH);
      cp_async16z(smem_u32(&Xs[cur ^ 1][kk_s][c_s * 4]),
                  xsrc + (size_t)(k0 + kk_s) * J, xp);
      cp_async16z(smem_u32(&Xs[cur ^ 1][kk_s][64 + c_s * 4]),
                  xsrc + (size_t)(k0 + kk_s) * J + 64, xp);
      CP_COMMIT();
#pragma unroll
      for (int q = 0; q < 2; q++) {
        int kb = k0 + kq * 8 + q * 4;
        wr[q] = make_float4(0.f, 0.f, 0.f, 0.f);
        if (wok && kb < FH)
          wr[q] = *reinterpret_cast<const float4*>(wptr + kb);
      }
    }
#pragma unroll
    for (int kk = 0; kk < 16; kk++) {
      float4 a0 = *reinterpret_cast<const float4*>(&Ws[cur][kk][ty * 4]);
      float4 a1 = *reinterpret_cast<const float4*>(&Ws[cur][kk][ty * 4 + 64]);
      ulonglong2 bq0 = *reinterpret_cast<const ulonglong2*>(&Xs[cur][kk][tx * 4]);
      ulonglong2 bq1 = *reinterpret_cast<const ulonglong2*>(&Xs[cur][kk][tx * 4 + 64]);
      unsigned long long bp[4] = {bq0.x, bq0.y, bq1.x, bq1.y};
      float av[8] = {a0.x, a0.y, a0.z, a0.w, a1.x, a1.y, a1.z, a1.w};
#pragma unroll
      for (int i = 0; i < 8; i++) {
        unsigned long long ap = pack2(av[i]);
#pragma unroll
        for (int p = 0; p < 4; p++) fma2(acc2[i][p], ap, bp[p]);
      }
    }
    if (more) {
#pragma unroll
      for (int q = 0; q < 2; q++) {
        Ws[cur ^ 1][kq * 8 + q * 4 + 0][fi_s] = wr[q].x;
        Ws[cur ^ 1][kq * 8 + q * 4 + 1][fi_s] = wr[q].y;
        Ws[cur ^ 1][kq * 8 + q * 4 + 2][fi_s] = wr[q].z;
        Ws[cur ^ 1][kq * 8 + q * 4 + 3][fi_s] = wr[q].w;
      }
      CP_WAIT0();
      __syncthreads();
    }
  }

#pragma unroll
  for (int i = 0; i < 8; i++) {
    int f = f0 + ((i < 4) ? (ty * 4 + i) : (64 + ty * 4 + i - 4));
    if (f >= FH) continue;
    float bb = b2[f];
#pragma unroll
    for (int h = 0; h < 2; h++) {
      int jb = j0 + h * 64 + tx * 4;
      float2 c0 = unpack2(acc2[i][h * 2]);
      float2 c1 = unpack2(acc2[i][h * 2 + 1]);
      float ac[4] = {c0.x, c0.y, c1.x, c1.y};
      float o[4];
#pragma unroll
      for (int r = 0; r < 4; r++)
        o[r] = __fadd_rn(ac[r], bb);
      *reinterpret_cast<float4*>(g_cur2 + (size_t)f * J + jb) =
          make_float4(o[0], o[1], o[2], o[3]);
    }
  }
}

// ---------------- kernel 4: LIF + second IIR: g_cur2 -> g_psp3 ---------------
__global__ __launch_bounds__(256) void lifiir_kernel() {
  __shared__ float s[64 * 101];
  size_t row0 = (size_t)blockIdx.x * 64;
  int tid = threadIdx.x;
  for (int i = tid; i < 6400; i += 256) {
    int r = i / 100, t = i - r * 100;
    s[r * 101 + t] = g_cur2[row0 * 100 + i];
  }
  __syncthreads();
  if (tid < 64) {
    float v = 0.f, sp = 0.f, y1 = 0.f, y2 = 0.f;
    float* row = s + tid * 101;
#pragma unroll
    for (int t = 0; t < NT; t++) {
      v = __fadd_rn(__fmul_rn(__fmul_rn(v, EMC), __fadd_rn(1.0f, -sp)), row[t]);
      sp = (v > 1.0f) ? 1.0f : 0.f;
      float y = __fadd_rn(__fadd_rn(__fmul_rn(A1C, y1), __fmul_rn(A2C, y2)), sp);
      row[t] = y;
      y2 = y1; y1 = y;
    }
  }
  __syncthreads();
  for (int i = tid; i < 6400; i += 256) {
    int r = i / 100, t = i - r * 100;
    g_psp3[row0 * 100 + i] = s[r * 101 + t];
  }
}

// ---------------- kernel 5: GEMM3 -> g_cur3[o][J] ----------------------------
__global__ __launch_bounds__(128) void gemm3_kernel(
    const float* __restrict__ W3, const float* __restrict__ b3) {
  __shared__ float Wsm[10 * 512];
  __shared__ float Xs[64][64];
  int j0 = blockIdx.x * 64;
  int tid = threadIdx.x;
  int jj = tid & 63, og = tid >> 6;      // og in {0,1}
  for (int i = tid; i < 10 * 512; i += 128) {
    int o = i >> 9, k = i & 511;
    Wsm[i] = (k < FH) ? W3[o * FH + k] : 0.f;
  }
  __syncthreads();
  float acc[5] = {0.f, 0.f, 0.f, 0.f, 0.f};
#pragma unroll 1
  for (int k0 = 0; k0 < 512; k0 += 64) {
#pragma unroll
    for (int s = 0; s < 8; s++) {
      int i = tid + s * 128;
      int kk = i >> 4, c4 = i & 15;
      int k = k0 + kk;
      float4 v = make_float4(0.f, 0.f, 0.f, 0.f);
      if (k < FH)
        v = *reinterpret_cast<const float4*>(g_psp3 + (size_t)k * J + j0 + c4 * 4);
      *reinterpret_cast<float4*>(&Xs[kk][c4 * 4]) = v;
    }
    __syncthreads();
#pragma unroll 16
    for (int kk = 0; kk < 64; kk++) {
      float x = Xs[kk][jj];
      int k = k0 + kk;
#pragma unroll
      for (int o = 0; o < 5; o++)
        acc[o] = fmaf(Wsm[(og * 5 + o) * 512 + k], x, acc[o]);
    }
    __syncthreads();
  }
#pragma unroll
  for (int o = 0; o < 5; o++) {
    int oo = og * 5 + o;
    g_cur3[(size_t)oo * J + j0 + jj] = __fadd_rn(acc[o], b3[oo]);
  }
}

// ---------------- kernel 6: LIF layer 3 -> out[b][o][t] ----------------------
__global__ __launch_bounds__(256) void lif3_out_kernel(float* __restrict__ out) {
  __shared__ float s[64 * 101];
  int rid0 = blockIdx.x * 64;     // rid = o*256 + b
  int tid = threadIdx.x;
  for (int i = tid; i < 6400; i += 256) {
    int r = i / 100, t = i - r * 100;
    s[r * 101 + t] = g_cur3[(size_t)rid0 * 100 + i];
  }
  __syncthreads();
  if (tid < 64) {
    int rid = rid0 + tid;
    int o = rid >> 8, b = rid & 255;
    float* po = out + ((size_t)b * 10 + o) * NT;
    const float* row = s + tid * 101;
    float v = 0.f, sp = 0.f;
#pragma unroll
    for (int t = 0; t < NT; t++) {
      v = __fadd_rn(__fmul_rn(__fmul_rn(v, EMC), __fadd_rn(1.0f, -sp)), row[t]);
      sp = (v > 1.0f) ? 1.0f : 0.f;
      po[t] = sp;
    }
  }
}

// ---------------- launcher ---------------------------------------------------
extern "C" void kernel_launch(void* const* d_in, const int* in_sizes, int n_in,
                              void* d_out, int out_size) {
  const float *X = nullptr, *W1 = nullptr, *b1 = nullptr, *W2 = nullptr,
              *b2 = nullptr, *W3 = nullptr, *b3 = nullptr;
  for (int i = 0; i < n_in; i++) {
    switch (in_sizes[i]) {
      case 20070400: X  = (const float*)d_in[i]; break;  // 256*784*100
      case 784000:   W1 = (const float*)d_in[i]; break;  // 1000*784
      case 1000:     b1 = (const float*)d_in[i]; break;
      case 250000:   W2 = (const float*)d_in[i]; break;  // 500*500
      case 500:      b2 = (const float*)d_in[i]; break;
      case 5000:     W3 = (const float*)d_in[i]; break;  // 10*500
      case 10:       b3 = (const float*)d_in[i]; break;
      default: break;
    }
  }
  float* out = (float*)d_out;

  gemm1_kernel<<<dim3(200, 8), 256>>>(X, W1, b1);
  iir_kernel<<<2000, 256>>>();
  gemm2_kernel<<<dim3(200, 4), 256>>>(W2, b2);
  lifiir_kernel<<<2000, 256>>>();
  gemm3_kernel<<<400, 128>>>(W3, b3);
  lif3_out_kernel<<<40, 256>>>(out);
}